// round 4
// baseline (speedup 1.0000x reference)
#include <cuda_runtime.h>
#include <cuda_bf16.h>
#include <cstdint>

#define M_DIM 16384
#define N_DIM 4096
#define K_DIM 4096
#define NCHUNK 4

// tcgen05 available only in an arch-specific (sm_103a/sm_100a) device pass
#if defined(__CUDA_ARCH__) && (defined(__CUDA_ARCH_FEAT_SM103_ALL) || defined(__CUDA_ARCH_FEAT_SM100_ALL) || defined(__CUDA_ARCH_FEAT_SM101_ALL))
#define HAS_TC 1
#else
#define HAS_TC 0
#endif

// Scratch
__device__ __nv_bfloat16 g_qx[(size_t)M_DIM * K_DIM];
__device__ __nv_bfloat16 g_qw[(size_t)N_DIM * K_DIM];
__device__ unsigned g_absmax_bits[8];

// ---------------------------------------------------------------------------
__global__ void zero_kernel() {
    if (threadIdx.x < 8) g_absmax_bits[threadIdx.x] = 0u;
}

__global__ void absmax_kernel(const float* __restrict__ src, int n, int is_w) {
    __shared__ unsigned smax[5];
    if (threadIdx.x < 5) smax[threadIdx.x] = 0u;
    __syncthreads();
    size_t stride = (size_t)gridDim.x * blockDim.x * 4;
    size_t base = ((size_t)blockIdx.x * blockDim.x + threadIdx.x) * 4;
    int c = is_w ? 4 : (int)((base & 4095) >> 10);
    float m = 0.f;
    for (size_t e = base; e < (size_t)n; e += stride) {
        float4 v = *(const float4*)(src + e);
        m = fmaxf(m, fmaxf(fmaxf(fabsf(v.x), fabsf(v.y)),
                           fmaxf(fabsf(v.z), fabsf(v.w))));
    }
    atomicMax(&smax[c], __float_as_uint(m));
    __syncthreads();
    if (threadIdx.x < 5) atomicMax(&g_absmax_bits[threadIdx.x], smax[threadIdx.x]);
}

__device__ __forceinline__ float quant_scale(int slot) {
    return fmaxf(__uint_as_float(g_absmax_bits[slot]) * (1.0f / 127.0f), 1e-8f);
}

__global__ void quant_x_kernel(const float* __restrict__ x, int n) {
    float inv[NCHUNK];
#pragma unroll
    for (int c = 0; c < NCHUNK; c++) inv[c] = 1.0f / quant_scale(c);
    size_t stride = (size_t)gridDim.x * blockDim.x * 4;
    size_t base = ((size_t)blockIdx.x * blockDim.x + threadIdx.x) * 4;
    for (size_t e = base; e < (size_t)n; e += stride) {
        int c = (int)((e & 4095) >> 10);
        float4 v = *(const float4*)(x + e);
        float q0 = fminf(fmaxf(rintf(v.x * inv[c]), -127.f), 127.f);
        float q1 = fminf(fmaxf(rintf(v.y * inv[c]), -127.f), 127.f);
        float q2 = fminf(fmaxf(rintf(v.z * inv[c]), -127.f), 127.f);
        float q3 = fminf(fmaxf(rintf(v.w * inv[c]), -127.f), 127.f);
        __nv_bfloat162 p0, p1;
        p0.x = __float2bfloat16_rn(q0); p0.y = __float2bfloat16_rn(q1);
        p1.x = __float2bfloat16_rn(q2); p1.y = __float2bfloat16_rn(q3);
        *(__nv_bfloat162*)(&g_qx[e])     = p0;
        *(__nv_bfloat162*)(&g_qx[e + 2]) = p1;
    }
}

__global__ void quant_w_kernel(const float* __restrict__ w, int n) {
    float inv = 1.0f / quant_scale(4);
    size_t stride = (size_t)gridDim.x * blockDim.x * 4;
    size_t base = ((size_t)blockIdx.x * blockDim.x + threadIdx.x) * 4;
    for (size_t e = base; e < (size_t)n; e += stride) {
        float4 v = *(const float4*)(w + e);
        float q0 = fminf(fmaxf(rintf(v.x * inv), -127.f), 127.f);
        float q1 = fminf(fmaxf(rintf(v.y * inv), -127.f), 127.f);
        float q2 = fminf(fmaxf(rintf(v.z * inv), -127.f), 127.f);
        float q3 = fminf(fmaxf(rintf(v.w * inv), -127.f), 127.f);
        __nv_bfloat162 p0, p1;
        p0.x = __float2bfloat16_rn(q0); p0.y = __float2bfloat16_rn(q1);
        p1.x = __float2bfloat16_rn(q2); p1.y = __float2bfloat16_rn(q3);
        *(__nv_bfloat162*)(&g_qw[e])     = p0;
        *(__nv_bfloat162*)(&g_qw[e + 2]) = p1;
    }
}

// ===========================================================================
// PATH 1: cg2 tcgen05 GEMM. Pair tile M=256 x N=256, K staged 64, 4 stages.
// Each CTA holds its M-half of A and its N-half of B (16KB + 16KB per stage).
// ===========================================================================
#define BMP 256               // pair M tile
#define BNP 256               // pair N tile
#define SK 64
#define STAGES 4
#define NITER (K_DIM / SK)            // 64
#define A_STAGE_BYTES (128 * 128)     // 16KB (this CTA's 128 A rows)
#define B_STAGE_BYTES (128 * 128)     // 16KB (this CTA's 128 B rows)
#define STAGE_BYTES (A_STAGE_BYTES + B_STAGE_BYTES)  // 32KB
#define SMEM_STAGE0 1024
#define SMEM_TOTAL (SMEM_STAGE0 + STAGES * STAGE_BYTES)  // 132096

// idesc: f32 accum, bf16 a/b, M=256 (bits24..=16), N=256 (bits17..=32)
#define MMA_IDESC ((16u << 24) | (32u << 17) | (1u << 10) | (1u << 7) | (1u << 4))

static constexpr uint64_t DESC_BASE_SW128 =
    (uint64_t(2) << 61) | (uint64_t(1) << 46) | (uint64_t(64) << 32) | (uint64_t(1) << 16);

__device__ __forceinline__ uint32_t smem_u32(const void* p) {
    return (uint32_t)__cvta_generic_to_shared(p);
}
__device__ __forceinline__ uint32_t swz(uint32_t o) { return o ^ ((o >> 3) & 0x70); }

__device__ __forceinline__ void cp16(uint32_t sdst, const void* gsrc) {
    asm volatile("cp.async.cg.shared.global [%0], [%1], 16;\n" :: "r"(sdst), "l"(gsrc));
}
#define CPA_COMMIT asm volatile("cp.async.commit_group;\n" ::: "memory")
#define CPA_WAIT(N) asm volatile("cp.async.wait_group %0;\n" :: "n"(N) : "memory")

#define MBAR_INIT(a, n) asm volatile("mbarrier.init.shared.b64 [%0], %1;" :: "r"(a), "r"(n) : "memory")
#define MBAR_INVAL(a)   asm volatile("mbarrier.inval.shared.b64 [%0];" :: "r"(a) : "memory")

__device__ __forceinline__ void mbar_wait(uint32_t addr, uint32_t parity) {
    asm volatile(
        "{\n\t.reg .pred P;\n\t"
        "WAIT_%=:\n\t"
        "mbarrier.try_wait.parity.acquire.cta.shared::cta.b64 P, [%0], %1, 0x989680;\n\t"
        "@P bra.uni DONE_%=;\n\t"
        "bra.uni WAIT_%=;\n\t"
        "DONE_%=:\n\t}"
        :: "r"(addr), "r"(parity) : "memory");
}

#define CLUSTER_ARRIVE() asm volatile("barrier.cluster.arrive.aligned;" ::: "memory")
#define CLUSTER_WAIT()   asm volatile("barrier.cluster.wait.aligned;" ::: "memory")

__device__ __forceinline__ uint32_t ctarank() {
    uint32_t r;
    asm("mov.u32 %0, %%cluster_ctarank;" : "=r"(r));
    return r;
}

#if HAS_TC
#define TC_ALLOC2(sp, n)   asm volatile("tcgen05.alloc.cta_group::2.sync.aligned.shared::cta.b32 [%0], %1;" :: "r"(sp), "r"(n) : "memory")
#define TC_DEALLOC2(t, n)  asm volatile("tcgen05.dealloc.cta_group::2.sync.aligned.b32 %0, %1;" :: "r"(t), "r"(n))
#define TC_RELINQ2()       asm volatile("tcgen05.relinquish_alloc_permit.cta_group::2.sync.aligned;")
#define TC_COMMIT_MC2(mb)  asm volatile("tcgen05.commit.cta_group::2.mbarrier::arrive::one.shared::cluster.multicast::cluster.b64 [%0], %1;" :: "r"(mb), "h"((uint16_t)0x3) : "memory")
#define TC_WAIT_LD()       asm volatile("tcgen05.wait::ld.sync.aligned;" ::: "memory")
#define TC_WAIT_ST()       asm volatile("tcgen05.wait::st.sync.aligned;" ::: "memory")
#define TC_FENCE_BEFORE()  asm volatile("tcgen05.fence::before_thread_sync;" ::: "memory")
#define TC_FENCE_AFTER()   asm volatile("tcgen05.fence::after_thread_sync;" ::: "memory")
#define FENCE_ASYNC()      asm volatile("fence.proxy.async.shared::cta;" ::: "memory")

// arrive on rank-0 CTA's mbarrier at the same smem offset
#define MBAR_ARRIVE_RANK0(addr) \
    asm volatile( \
        "{\n\t.reg .b32 ra;\n\t" \
        "mapa.shared::cluster.u32 ra, %0, %1;\n\t" \
        "mbarrier.arrive.shared::cluster.b64 _, [ra];\n\t}" \
        :: "r"(addr), "r"(0) : "memory")

__device__ __forceinline__ void mma_f16_ss_cg2(uint32_t d, uint64_t ad, uint64_t bd,
                                               uint32_t idesc, uint32_t en) {
    asm volatile(
        "{\n\t.reg .pred p;\n\t"
        "setp.ne.u32 p, %4, 0;\n\t"
        "tcgen05.mma.cta_group::2.kind::f16 [%0], %1, %2, %3, {%5,%5,%5,%5,%5,%5,%5,%5}, p;\n\t}"
        :: "r"(d), "l"(ad), "l"(bd), "r"(idesc), "r"(en), "r"(0u) : "memory");
}

#define TC_LD32(r, addr) \
    asm volatile( \
        "tcgen05.ld.sync.aligned.32x32b.x32.b32 " \
        "{%0,%1,%2,%3,%4,%5,%6,%7,%8,%9,%10,%11,%12,%13,%14,%15," \
        "%16,%17,%18,%19,%20,%21,%22,%23,%24,%25,%26,%27,%28,%29,%30,%31}, [%32];" \
        : "=r"((r)[0]),"=r"((r)[1]),"=r"((r)[2]),"=r"((r)[3]),"=r"((r)[4]),"=r"((r)[5]),"=r"((r)[6]),"=r"((r)[7]), \
          "=r"((r)[8]),"=r"((r)[9]),"=r"((r)[10]),"=r"((r)[11]),"=r"((r)[12]),"=r"((r)[13]),"=r"((r)[14]),"=r"((r)[15]), \
          "=r"((r)[16]),"=r"((r)[17]),"=r"((r)[18]),"=r"((r)[19]),"=r"((r)[20]),"=r"((r)[21]),"=r"((r)[22]),"=r"((r)[23]), \
          "=r"((r)[24]),"=r"((r)[25]),"=r"((r)[26]),"=r"((r)[27]),"=r"((r)[28]),"=r"((r)[29]),"=r"((r)[30]),"=r"((r)[31]) \
        : "r"(addr))

#define TC_ST32(addr, r) \
    asm volatile( \
        "tcgen05.st.sync.aligned.32x32b.x32.b32 [%0], " \
        "{%1,%2,%3,%4,%5,%6,%7,%8,%9,%10,%11,%12,%13,%14,%15,%16," \
        "%17,%18,%19,%20,%21,%22,%23,%24,%25,%26,%27,%28,%29,%30,%31,%32};" \
        :: "r"(addr), \
           "r"((r)[0]),"r"((r)[1]),"r"((r)[2]),"r"((r)[3]),"r"((r)[4]),"r"((r)[5]),"r"((r)[6]),"r"((r)[7]), \
           "r"((r)[8]),"r"((r)[9]),"r"((r)[10]),"r"((r)[11]),"r"((r)[12]),"r"((r)[13]),"r"((r)[14]),"r"((r)[15]), \
           "r"((r)[16]),"r"((r)[17]),"r"((r)[18]),"r"((r)[19]),"r"((r)[20]),"r"((r)[21]),"r"((r)[22]),"r"((r)[23]), \
           "r"((r)[24]),"r"((r)[25]),"r"((r)[26]),"r"((r)[27]),"r"((r)[28]),"r"((r)[29]),"r"((r)[30]),"r"((r)[31]) \
        : "memory")
#endif  // HAS_TC

__global__ void __launch_bounds__(256, 1) __cluster_dims__(2, 1, 1)
gemm_tc_kernel(const float* __restrict__ bias, float* __restrict__ out) {
#if HAS_TC
    extern __shared__ char smem[];
    const uint32_t sbase = smem_u32(smem);
    const int tid = threadIdx.x;
    const int warp = tid >> 5;
    const uint32_t rank = ctarank();
    const int bn = blockIdx.x >> 1;     // pair N tile
    const int bm = blockIdx.y;          // pair M tile

    // barriers: full[0..3] at +16, empty[0..3] at +48, chunk +80, final +88
    const uint32_t mb_full  = sbase + 16;
    const uint32_t mb_empty = sbase + 48;
    const uint32_t mb_chunk = sbase + 80;
    const uint32_t mb_final = sbase + 88;

    if (tid == 0) {
#pragma unroll
        for (int s = 0; s < STAGES; s++) {
            MBAR_INIT(mb_full + s * 8, 2);   // both CTAs arrive
            MBAR_INIT(mb_empty + s * 8, 1);  // multicast commit arrival
        }
        MBAR_INIT(mb_chunk, 1);
        MBAR_INIT(mb_final, 1);
    }
    if (warp == 0) { TC_ALLOC2(sbase, 512); TC_RELINQ2(); }
    __syncthreads();
    // all mbarriers + TMEM alloc visible cluster-wide before any cross-CTA op
    CLUSTER_ARRIVE();
    CLUSTER_WAIT();

    uint32_t tmem_base;
    asm volatile("ld.shared.b32 %0, [%1];" : "=r"(tmem_base) : "r"(sbase));

    float cs[NCHUNK];
    {
        float sw = quant_scale(4);
#pragma unroll
        for (int c = 0; c < NCHUNK; c++) cs[c] = quant_scale(c) * sw;
    }

    // This CTA's operand slices: A rows = its M half, B rows = its N half.
    const __nv_bfloat16* gA = g_qx + (size_t)(bm * BMP + rank * 128) * K_DIM;
    const __nv_bfloat16* gB = g_qw + (size_t)(bn * BNP + rank * 128) * K_DIM;

    auto produce = [&](int t) {
        const int slot = t & (STAGES - 1);
        const uint32_t abase = sbase + SMEM_STAGE0 + slot * STAGE_BYTES;
        const uint32_t bbase = abase + A_STAGE_BYTES;
        const int kt = t * SK;
#pragma unroll
        for (int j = 0; j < 4; j++) {       // A: 1024 16B chunks / 256 thr
            int ch = tid + j * 256;
            int row = ch >> 3, c16 = ch & 7;
            cp16(abase + swz(row * 128 + c16 * 16),
                 gA + (size_t)row * K_DIM + kt + c16 * 8);
        }
#pragma unroll
        for (int j = 0; j < 4; j++) {       // B: 1024 16B chunks / 256 thr
            int ch = tid + j * 256;
            int row = ch >> 3, c16 = ch & 7;
            cp16(bbase + swz(row * 128 + c16 * 16),
                 gB + (size_t)row * K_DIM + kt + c16 * 8);
        }
    };

#pragma unroll
    for (int t = 0; t < STAGES - 1; t++) {
        produce(t);
        CPA_COMMIT;
    }

    for (int i = 0; i < NITER; ++i) {
        // wait this CTA's cp.asyncs for stage i
        if (i <= NITER - 3) { CPA_WAIT(2); }
        else if (i == NITER - 2) { CPA_WAIT(1); }
        else { CPA_WAIT(0); }
        __syncthreads();

        // signal stage-i data ready to the leader (both CTAs arrive)
        if (tid == 0) {
            FENCE_ASYNC();
            MBAR_ARRIVE_RANK0(mb_full + (i & (STAGES - 1)) * 8);
        }

        // chunk-boundary in-place accumulator rescale (both CTAs, own lanes)
        if (i == 16 || i == 48) {
            if (tid < 128) {
                mbar_wait(mb_chunk, (i == 16) ? 0u : 1u);
                TC_FENCE_AFTER();
                const float ratio = (i == 16) ? (cs[0] / cs[1]) : (cs[2] / cs[3]);
                const uint32_t accoff = (i == 16) ? 0u : 256u;
                const uint32_t woff = (uint32_t)(tid >> 5) << 21;
#pragma unroll
                for (int nb = 0; nb < 8; nb++) {
                    uint32_t r[32];
                    TC_LD32(r, tmem_base + accoff + nb * 32);
                    TC_WAIT_LD();
#pragma unroll
                    for (int j = 0; j < 32; j++)
                        r[j] = __float_as_uint(__uint_as_float(r[j]) * ratio);
                    TC_ST32(tmem_base + accoff + nb * 32 + woff, r);
                    TC_WAIT_ST();
                }
                TC_FENCE_BEFORE();
            }
            __syncthreads();
            // both CTAs must finish rescale before leader restarts MMA
            CLUSTER_ARRIVE();
            CLUSTER_WAIT();
        }

        // MMA issue: leader CTA, single thread
        if (rank == 0 && tid == 0) {
            const int slot = i & (STAGES - 1);
            mbar_wait(mb_full + slot * 8, (uint32_t)((i >> 2) & 1));
            if (i == 16 || i == 48) TC_FENCE_AFTER();
            const uint32_t abase = sbase + SMEM_STAGE0 + slot * STAGE_BYTES;
            const uint64_t ad = DESC_BASE_SW128 | ((uint64_t)(abase >> 4) & 0x3FFF);
            const uint64_t bd = DESC_BASE_SW128 | ((uint64_t)((abase + A_STAGE_BYTES) >> 4) & 0x3FFF);
            const uint32_t d = tmem_base + ((i < 32) ? 0u : 256u);
            const uint32_t en0 = (i == 0 || i == 32) ? 0u : 1u;
#pragma unroll
            for (int k = 0; k < 4; k++)
                mma_f16_ss_cg2(d, ad + k * 2, bd + k * 2, MMA_IDESC, (k > 0) ? 1u : en0);
            TC_COMMIT_MC2(mb_empty + slot * 8);
            if (i == 15 || i == 47) TC_COMMIT_MC2(mb_chunk);
            if (i == NITER - 1) TC_COMMIT_MC2(mb_final);
        }

        // produce stage i+3 once its slot is recycled
        if (i < NITER - (STAGES - 1)) {
            const int t = i + STAGES - 1;
            if (t >= STAGES)
                mbar_wait(mb_empty + (t & (STAGES - 1)) * 8, (uint32_t)(((t >> 2) - 1) & 1));
            produce(t);
            CPA_COMMIT;
        }
    }

    // epilogue: each CTA reads its 128 TMEM lanes (its M half), full N=256
    mbar_wait(mb_final, 0u);
    TC_FENCE_AFTER();
    if (tid < 128) {
        const float sA = cs[1], sB = cs[3];
        const int row = bm * BMP + (int)rank * 128 + tid;
        float* orow = out + (size_t)row * N_DIM + bn * BNP;
        const float* brow = bias + bn * BNP;
#pragma unroll
        for (int nb = 0; nb < 8; nb++) {
            uint32_t a[32], b[32];
            TC_LD32(a, tmem_base + nb * 32);
            TC_LD32(b, tmem_base + 256 + nb * 32);
            TC_WAIT_LD();
#pragma unroll
            for (int j = 0; j < 32; j += 4) {
                float4 bb = *(const float4*)(brow + nb * 32 + j);
                float4 v;
                v.x = __uint_as_float(a[j + 0]) * sA + __uint_as_float(b[j + 0]) * sB + bb.x;
                v.y = __uint_as_float(a[j + 1]) * sA + __uint_as_float(b[j + 1]) * sB + bb.y;
                v.z = __uint_as_float(a[j + 2]) * sA + __uint_as_float(b[j + 2]) * sB + bb.z;
                v.w = __uint_as_float(a[j + 3]) * sA + __uint_as_float(b[j + 3]) * sB + bb.w;
                *(float4*)(orow + nb * 32 + j) = v;
            }
        }
        TC_FENCE_BEFORE();
    }
    __syncthreads();
    if (tid == 0) { MBAR_INVAL(mb_chunk); MBAR_INVAL(mb_final); }
    if (warp == 0) { TC_DEALLOC2(tmem_base, 512); }
    // no CTA exits while peer may still touch its smem/TMEM
    CLUSTER_ARRIVE();
    CLUSTER_WAIT();
#endif  // HAS_TC
}

// ===========================================================================
// PATH 2: fallback mma.sync bf16 GEMM (active only when no tcgen05 in pass)
// ===========================================================================
#define FBM 128
#define FBN 128
#define FBK 32
#define FSTR 40

__device__ __forceinline__ void mma16816(float* c, const uint32_t* a, const uint32_t* b) {
    asm volatile(
        "mma.sync.aligned.m16n8k16.row.col.f32.bf16.bf16.f32 "
        "{%0,%1,%2,%3}, {%4,%5,%6,%7}, {%8,%9}, {%0,%1,%2,%3};\n"
        : "+f"(c[0]), "+f"(c[1]), "+f"(c[2]), "+f"(c[3])
        : "r"(a[0]), "r"(a[1]), "r"(a[2]), "r"(a[3]), "r"(b[0]), "r"(b[1]));
}

__global__ void __launch_bounds__(256) gemm_fb_kernel(const float* __restrict__ bias,
                                                      float* __restrict__ out) {
#if !HAS_TC
    __shared__ __nv_bfloat16 As[2][FBM * FSTR];
    __shared__ __nv_bfloat16 Bs[2][FBN * FSTR];

    const int bn = blockIdx.x, bm = blockIdx.y;
    const int tid = threadIdx.x;
    const int lane = tid & 31, warp = tid >> 5;
    const int g = lane >> 2, t4 = lane & 3;
    const int wm = (warp & 1) * 64;
    const int wn = (warp >> 1) * 32;

    float cs[NCHUNK];
    {
        float sw = quant_scale(4);
#pragma unroll
        for (int c = 0; c < NCHUNK; c++) cs[c] = quant_scale(c) * sw;
    }

    const int r = tid >> 1, kc = (tid & 1) * 16;
    const __nv_bfloat16* gA = g_qx + (size_t)(bm * FBM + r) * K_DIM + kc;
    const __nv_bfloat16* gB = g_qw + (size_t)(bn * FBN + r) * K_DIM + kc;

    auto cpa = [&](void* sdst, const void* gsrc) {
        unsigned sa = (unsigned)__cvta_generic_to_shared(sdst);
        asm volatile("cp.async.cg.shared.global [%0], [%1], 16;\n" :: "r"(sa), "l"(gsrc));
    };
    auto issue = [&](int stage) {
        int buf = stage & 1;
        int kt = stage * FBK;
        cpa(&As[buf][r * FSTR + kc],     gA + kt);
        cpa(&As[buf][r * FSTR + kc + 8], gA + kt + 8);
        cpa(&Bs[buf][r * FSTR + kc],     gB + kt);
        cpa(&Bs[buf][r * FSTR + kc + 8], gB + kt + 8);
    };

    float acc[4][4][4];
#pragma unroll
    for (int mt = 0; mt < 4; mt++)
#pragma unroll
        for (int nt = 0; nt < 4; nt++)
#pragma unroll
            for (int i = 0; i < 4; i++) acc[mt][nt][i] = 0.f;

    const int NIT = K_DIM / FBK;
    issue(0);
    CPA_COMMIT;

    for (int it = 0; it < NIT; ++it) {
        if (it + 1 < NIT) {
            issue(it + 1);
            CPA_COMMIT;
            CPA_WAIT(1);
        } else {
            CPA_WAIT(0);
        }
        __syncthreads();

        const __nv_bfloat16* sa = As[it & 1];
        const __nv_bfloat16* sb = Bs[it & 1];
#pragma unroll
        for (int kk = 0; kk < FBK; kk += 16) {
            uint32_t af[4][4], bfr[4][2];
#pragma unroll
            for (int mt = 0; mt < 4; mt++) {
                const __nv_bfloat16* p = sa + (wm + mt * 16 + g) * FSTR + kk + t4 * 2;
                af[mt][0] = *(const uint32_t*)p;
                af[mt][1] = *(const uint32_t*)(p + 8 * FSTR);
                af[mt][2] = *(const uint32_t*)(p + 8);
                af[mt][3] = *(const uint32_t*)(p + 8 * FSTR + 8);
            }
#pragma unroll
            for (int nt = 0; nt < 4; nt++) {
                const __nv_bfloat16* p = sb + (wn + nt * 8 + g) * FSTR + kk + t4 * 2;
                bfr[nt][0] = *(const uint32_t*)p;
                bfr[nt][1] = *(const uint32_t*)(p + 8);
            }
#pragma unroll
            for (int mt = 0; mt < 4; mt++)
#pragma unroll
                for (int nt = 0; nt < 4; nt++)
                    mma16816(acc[mt][nt], af[mt], bfr[nt]);
        }
        __syncthreads();

        if (((it + 1) & 31) == 0 && (it + 1) < NIT) {
            int c = ((it + 1) >> 5) - 1;
            float rt = cs[c] / cs[c + 1];
#pragma unroll
            for (int mt = 0; mt < 4; mt++)
#pragma unroll
                for (int nt = 0; nt < 4; nt++)
#pragma unroll
                    for (int i = 0; i < 4; i++) acc[mt][nt][i] *= rt;
        }
    }

    const float fs = cs[3];
#pragma unroll
    for (int mt = 0; mt < 4; mt++) {
        int row0 = bm * FBM + wm + mt * 16 + g;
#pragma unroll
        for (int nt = 0; nt < 4; nt++) {
            int col = bn * FBN + wn + nt * 8 + t4 * 2;
            float b0 = bias[col], b1 = bias[col + 1];
            float2 v0 = make_float2(acc[mt][nt][0] * fs + b0, acc[mt][nt][1] * fs + b1);
            float2 v1 = make_float2(acc[mt][nt][2] * fs + b0, acc[mt][nt][3] * fs + b1);
            *(float2*)(out + (size_t)row0 * N_DIM + col) = v0;
            *(float2*)(out + (size_t)(row0 + 8) * N_DIM + col) = v1;
        }
    }
#endif  // !HAS_TC
}

// ---------------------------------------------------------------------------
extern "C" void kernel_launch(void* const* d_in, const int* in_sizes, int n_in,
                              void* d_out, int out_size) {
    const float* x = (const float*)d_in[0];
    const float* w = (const float*)d_in[1];
    const float* bias = (const float*)d_in[2];
    float* out = (float*)d_out;

    const int nx = M_DIM * K_DIM;
    const int nw = N_DIM * K_DIM;

    zero_kernel<<<1, 32>>>();
    absmax_kernel<<<1024, 256>>>(x, nx, 0);
    absmax_kernel<<<512, 256>>>(w, nw, 1);
    quant_x_kernel<<<8192, 256>>>(x, nx);
    quant_w_kernel<<<2048, 256>>>(w, nw);

    cudaFuncSetAttribute(gemm_tc_kernel,
                         cudaFuncAttributeMaxDynamicSharedMemorySize, SMEM_TOTAL);
    dim3 gtc(2 * (N_DIM / BNP), M_DIM / BMP);  // (32, 64): 1024 pairs
    gemm_tc_kernel<<<gtc, 256, SMEM_TOTAL>>>(bias, out);

    dim3 gfb(N_DIM / FBN, M_DIM / FBM);
    gemm_fb_kernel<<<gfb, 256>>>(bias, out);
}

// round 5
// speedup vs baseline: 1.3523x; 1.3523x over previous
#include <cuda_runtime.h>
#include <cuda_bf16.h>
#include <cstdint>

#define M_DIM 16384
#define N_DIM 4096
#define K_DIM 4096
#define NCHUNK 4

// tcgen05 available only in an arch-specific (sm_103a/sm_100a) device pass
#if defined(__CUDA_ARCH__) && (defined(__CUDA_ARCH_FEAT_SM103_ALL) || defined(__CUDA_ARCH_FEAT_SM100_ALL) || defined(__CUDA_ARCH_FEAT_SM101_ALL))
#define HAS_TC 1
#else
#define HAS_TC 0
#endif

// Scratch
__device__ __nv_bfloat16 g_qx[(size_t)M_DIM * K_DIM];
__device__ __nv_bfloat16 g_qw[(size_t)N_DIM * K_DIM];
__device__ unsigned g_absmax_bits[8];

// ---------------------------------------------------------------------------
__global__ void zero_kernel() {
    if (threadIdx.x < 8) g_absmax_bits[threadIdx.x] = 0u;
}

__global__ void absmax_kernel(const float* __restrict__ src, int n, int is_w) {
    __shared__ unsigned smax[5];
    if (threadIdx.x < 5) smax[threadIdx.x] = 0u;
    __syncthreads();
    size_t stride = (size_t)gridDim.x * blockDim.x * 4;
    size_t base = ((size_t)blockIdx.x * blockDim.x + threadIdx.x) * 4;
    int c = is_w ? 4 : (int)((base & 4095) >> 10);
    float m = 0.f;
    for (size_t e = base; e < (size_t)n; e += stride) {
        float4 v = *(const float4*)(src + e);
        m = fmaxf(m, fmaxf(fmaxf(fabsf(v.x), fabsf(v.y)),
                           fmaxf(fabsf(v.z), fabsf(v.w))));
    }
    atomicMax(&smax[c], __float_as_uint(m));
    __syncthreads();
    if (threadIdx.x < 5) atomicMax(&g_absmax_bits[threadIdx.x], smax[threadIdx.x]);
}

__device__ __forceinline__ float quant_scale(int slot) {
    return fmaxf(__uint_as_float(g_absmax_bits[slot]) * (1.0f / 127.0f), 1e-8f);
}

__global__ void quant_x_kernel(const float* __restrict__ x, int n) {
    float inv[NCHUNK];
#pragma unroll
    for (int c = 0; c < NCHUNK; c++) inv[c] = 1.0f / quant_scale(c);
    size_t stride = (size_t)gridDim.x * blockDim.x * 4;
    size_t base = ((size_t)blockIdx.x * blockDim.x + threadIdx.x) * 4;
    for (size_t e = base; e < (size_t)n; e += stride) {
        int c = (int)((e & 4095) >> 10);
        float4 v = *(const float4*)(x + e);
        float q0 = fminf(fmaxf(rintf(v.x * inv[c]), -127.f), 127.f);
        float q1 = fminf(fmaxf(rintf(v.y * inv[c]), -127.f), 127.f);
        float q2 = fminf(fmaxf(rintf(v.z * inv[c]), -127.f), 127.f);
        float q3 = fminf(fmaxf(rintf(v.w * inv[c]), -127.f), 127.f);
        __nv_bfloat162 p0, p1;
        p0.x = __float2bfloat16_rn(q0); p0.y = __float2bfloat16_rn(q1);
        p1.x = __float2bfloat16_rn(q2); p1.y = __float2bfloat16_rn(q3);
        *(__nv_bfloat162*)(&g_qx[e])     = p0;
        *(__nv_bfloat162*)(&g_qx[e + 2]) = p1;
    }
}

__global__ void quant_w_kernel(const float* __restrict__ w, int n) {
    float inv = 1.0f / quant_scale(4);
    size_t stride = (size_t)gridDim.x * blockDim.x * 4;
    size_t base = ((size_t)blockIdx.x * blockDim.x + threadIdx.x) * 4;
    for (size_t e = base; e < (size_t)n; e += stride) {
        float4 v = *(const float4*)(w + e);
        float q0 = fminf(fmaxf(rintf(v.x * inv), -127.f), 127.f);
        float q1 = fminf(fmaxf(rintf(v.y * inv), -127.f), 127.f);
        float q2 = fminf(fmaxf(rintf(v.z * inv), -127.f), 127.f);
        float q3 = fminf(fmaxf(rintf(v.w * inv), -127.f), 127.f);
        __nv_bfloat162 p0, p1;
        p0.x = __float2bfloat16_rn(q0); p0.y = __float2bfloat16_rn(q1);
        p1.x = __float2bfloat16_rn(q2); p1.y = __float2bfloat16_rn(q3);
        *(__nv_bfloat162*)(&g_qw[e])     = p0;
        *(__nv_bfloat162*)(&g_qw[e + 2]) = p1;
    }
}

// ===========================================================================
// PATH 1: cg1 tcgen05 GEMM, 256x256 CTA tile (two M=128 halves -> TMEM cols
// 0 and 256). K staged 64 deep, 3 stages x 64KB. Single-CTA: no cluster.
// ===========================================================================
#define BT 256                // CTA tile (M and N)
#define SK 64
#define STAGES 3
#define NITER (K_DIM / SK)            // 64
#define A_STAGE_BYTES (256 * 128)     // 32KB
#define B_STAGE_BYTES (256 * 128)     // 32KB
#define STAGE_BYTES (A_STAGE_BYTES + B_STAGE_BYTES)  // 64KB
#define SMEM_STAGE0 1024
#define SMEM_TOTAL (SMEM_STAGE0 + STAGES * STAGE_BYTES)  // 197632

// idesc: f32 accum, bf16 a/b, M=128 (per half), N=256
#define MMA_IDESC ((8u << 24) | (32u << 17) | (1u << 10) | (1u << 7) | (1u << 4))

static constexpr uint64_t DESC_BASE_SW128 =
    (uint64_t(2) << 61) | (uint64_t(1) << 46) | (uint64_t(64) << 32) | (uint64_t(1) << 16);

__device__ __forceinline__ uint32_t smem_u32(const void* p) {
    return (uint32_t)__cvta_generic_to_shared(p);
}
__device__ __forceinline__ uint32_t swz(uint32_t o) { return o ^ ((o >> 3) & 0x70); }

__device__ __forceinline__ void cp16(uint32_t sdst, const void* gsrc) {
    asm volatile("cp.async.cg.shared.global [%0], [%1], 16;\n" :: "r"(sdst), "l"(gsrc));
}
#define CPA_COMMIT asm volatile("cp.async.commit_group;\n" ::: "memory")
#define CPA_WAIT(N) asm volatile("cp.async.wait_group %0;\n" :: "n"(N) : "memory")

#define MBAR_INIT(a, n) asm volatile("mbarrier.init.shared.b64 [%0], %1;" :: "r"(a), "r"(n) : "memory")
#define MBAR_INVAL(a)   asm volatile("mbarrier.inval.shared.b64 [%0];" :: "r"(a) : "memory")

__device__ __forceinline__ void mbar_wait(uint32_t addr, uint32_t parity) {
    asm volatile(
        "{\n\t.reg .pred P;\n\t"
        "WAIT_%=:\n\t"
        "mbarrier.try_wait.parity.acquire.cta.shared::cta.b64 P, [%0], %1, 0x989680;\n\t"
        "@P bra.uni DONE_%=;\n\t"
        "bra.uni WAIT_%=;\n\t"
        "DONE_%=:\n\t}"
        :: "r"(addr), "r"(parity) : "memory");
}

#if HAS_TC
#define TC_ALLOC(sp, n)   asm volatile("tcgen05.alloc.cta_group::1.sync.aligned.shared::cta.b32 [%0], %1;" :: "r"(sp), "r"(n) : "memory")
#define TC_DEALLOC(t, n)  asm volatile("tcgen05.dealloc.cta_group::1.sync.aligned.b32 %0, %1;" :: "r"(t), "r"(n))
#define TC_RELINQ()       asm volatile("tcgen05.relinquish_alloc_permit.cta_group::1.sync.aligned;")
#define TC_COMMIT(mb)     asm volatile("tcgen05.commit.cta_group::1.mbarrier::arrive::one.shared::cluster.b64 [%0];" :: "r"(mb) : "memory")
#define TC_WAIT_LD()      asm volatile("tcgen05.wait::ld.sync.aligned;" ::: "memory")
#define TC_WAIT_ST()      asm volatile("tcgen05.wait::st.sync.aligned;" ::: "memory")
#define TC_FENCE_BEFORE() asm volatile("tcgen05.fence::before_thread_sync;" ::: "memory")
#define TC_FENCE_AFTER()  asm volatile("tcgen05.fence::after_thread_sync;" ::: "memory")
#define FENCE_ASYNC()     asm volatile("fence.proxy.async.shared::cta;" ::: "memory")

__device__ __forceinline__ void mma_f16_ss(uint32_t d, uint64_t ad, uint64_t bd,
                                           uint32_t idesc, uint32_t en) {
    asm volatile(
        "{\n\t.reg .pred p;\n\t"
        "setp.ne.u32 p, %4, 0;\n\t"
        "tcgen05.mma.cta_group::1.kind::f16 [%0], %1, %2, %3, {%5,%5,%5,%5}, p;\n\t}"
        :: "r"(d), "l"(ad), "l"(bd), "r"(idesc), "r"(en), "r"(0u) : "memory");
}

#define TC_LD32(r, addr) \
    asm volatile( \
        "tcgen05.ld.sync.aligned.32x32b.x32.b32 " \
        "{%0,%1,%2,%3,%4,%5,%6,%7,%8,%9,%10,%11,%12,%13,%14,%15," \
        "%16,%17,%18,%19,%20,%21,%22,%23,%24,%25,%26,%27,%28,%29,%30,%31}, [%32];" \
        : "=r"((r)[0]),"=r"((r)[1]),"=r"((r)[2]),"=r"((r)[3]),"=r"((r)[4]),"=r"((r)[5]),"=r"((r)[6]),"=r"((r)[7]), \
          "=r"((r)[8]),"=r"((r)[9]),"=r"((r)[10]),"=r"((r)[11]),"=r"((r)[12]),"=r"((r)[13]),"=r"((r)[14]),"=r"((r)[15]), \
          "=r"((r)[16]),"=r"((r)[17]),"=r"((r)[18]),"=r"((r)[19]),"=r"((r)[20]),"=r"((r)[21]),"=r"((r)[22]),"=r"((r)[23]), \
          "=r"((r)[24]),"=r"((r)[25]),"=r"((r)[26]),"=r"((r)[27]),"=r"((r)[28]),"=r"((r)[29]),"=r"((r)[30]),"=r"((r)[31]) \
        : "r"(addr))

#define TC_ST32(addr, r) \
    asm volatile( \
        "tcgen05.st.sync.aligned.32x32b.x32.b32 [%0], " \
        "{%1,%2,%3,%4,%5,%6,%7,%8,%9,%10,%11,%12,%13,%14,%15,%16," \
        "%17,%18,%19,%20,%21,%22,%23,%24,%25,%26,%27,%28,%29,%30,%31,%32};" \
        :: "r"(addr), \
           "r"((r)[0]),"r"((r)[1]),"r"((r)[2]),"r"((r)[3]),"r"((r)[4]),"r"((r)[5]),"r"((r)[6]),"r"((r)[7]), \
           "r"((r)[8]),"r"((r)[9]),"r"((r)[10]),"r"((r)[11]),"r"((r)[12]),"r"((r)[13]),"r"((r)[14]),"r"((r)[15]), \
           "r"((r)[16]),"r"((r)[17]),"r"((r)[18]),"r"((r)[19]),"r"((r)[20]),"r"((r)[21]),"r"((r)[22]),"r"((r)[23]), \
           "r"((r)[24]),"r"((r)[25]),"r"((r)[26]),"r"((r)[27]),"r"((r)[28]),"r"((r)[29]),"r"((r)[30]),"r"((r)[31]) \
        : "memory")
#endif  // HAS_TC

__global__ void __launch_bounds__(256, 1) gemm_tc_kernel(const float* __restrict__ bias,
                                                         float* __restrict__ out) {
#if HAS_TC
    extern __shared__ char smem[];
    const uint32_t sbase = smem_u32(smem);
    const int tid = threadIdx.x;
    const int warp = tid >> 5;
    const int bn = blockIdx.x, bm = blockIdx.y;

    // barriers: empty[0..2] at +16, chunk at +48, final at +56
    const uint32_t mb_empty = sbase + 16;
    const uint32_t mb_chunk = sbase + 48;
    const uint32_t mb_final = sbase + 56;

    if (tid == 0) {
#pragma unroll
        for (int s = 0; s < STAGES; s++) MBAR_INIT(mb_empty + s * 8, 1);
        MBAR_INIT(mb_chunk, 1);
        MBAR_INIT(mb_final, 1);
    }
    if (warp == 0) { TC_ALLOC(sbase, 512); TC_RELINQ(); }
    __syncthreads();

    uint32_t tmem_base;
    asm volatile("ld.shared.b32 %0, [%1];" : "=r"(tmem_base) : "r"(sbase));

    float cs[NCHUNK];
    {
        float sw = quant_scale(4);
#pragma unroll
        for (int c = 0; c < NCHUNK; c++) cs[c] = quant_scale(c) * sw;
    }

    const __nv_bfloat16* gA = g_qx + (size_t)(bm * BT) * K_DIM;
    const __nv_bfloat16* gB = g_qw + (size_t)(bn * BT) * K_DIM;

    auto produce = [&](int t) {
        const int slot = t % STAGES;
        const uint32_t abase = sbase + SMEM_STAGE0 + slot * STAGE_BYTES;
        const uint32_t bbase = abase + A_STAGE_BYTES;
        const int kt = t * SK;
#pragma unroll
        for (int j = 0; j < 8; j++) {       // A: 2048 16B chunks / 256 thr
            int ch = tid + j * 256;
            int row = ch >> 3, c16 = ch & 7;
            cp16(abase + swz(row * 128 + c16 * 16),
                 gA + (size_t)row * K_DIM + kt + c16 * 8);
        }
#pragma unroll
        for (int j = 0; j < 8; j++) {       // B: 2048 16B chunks / 256 thr
            int ch = tid + j * 256;
            int row = ch >> 3, c16 = ch & 7;
            cp16(bbase + swz(row * 128 + c16 * 16),
                 gB + (size_t)row * K_DIM + kt + c16 * 8);
        }
    };

    // prologue: fill stages 0..1
#pragma unroll
    for (int t = 0; t < STAGES - 1; t++) {
        produce(t);
        CPA_COMMIT;
    }

    for (int i = 0; i < NITER; ++i) {
        // stage i's cp.async groups done (outstanding: i, i+1)
        if (i <= NITER - 2) { CPA_WAIT(1); }
        else { CPA_WAIT(0); }
        __syncthreads();

        // chunk-boundary in-place accumulator rescale (all 512 cols)
        if (i == 16 || i == 32 || i == 48) {
            if (tid < 128) {
                mbar_wait(mb_chunk, (uint32_t)(((i >> 4) - 1) & 1));
                TC_FENCE_AFTER();
                const int c = (i >> 4) - 1;  // chunk just completed
                const float ratio = cs[c] / cs[c + 1];
                const uint32_t woff = (uint32_t)(tid >> 5) << 21;
#pragma unroll
                for (int nb = 0; nb < 16; nb++) {
                    uint32_t r[32];
                    TC_LD32(r, tmem_base + nb * 32);
                    TC_WAIT_LD();
#pragma unroll
                    for (int j = 0; j < 32; j++)
                        r[j] = __float_as_uint(__uint_as_float(r[j]) * ratio);
                    TC_ST32(tmem_base + nb * 32 + woff, r);
                    TC_WAIT_ST();
                }
                TC_FENCE_BEFORE();
            }
            __syncthreads();
        }

        // MMA issue (single thread): two M=128 halves per K-step
        if (tid == 0) {
            FENCE_ASYNC();
            if (i == 16 || i == 32 || i == 48) TC_FENCE_AFTER();
            const int slot = i % STAGES;
            const uint32_t abase = sbase + SMEM_STAGE0 + slot * STAGE_BYTES;
            const uint64_t ad = DESC_BASE_SW128 | ((uint64_t)(abase >> 4) & 0x3FFF);
            const uint64_t bd = DESC_BASE_SW128 | ((uint64_t)((abase + A_STAGE_BYTES) >> 4) & 0x3FFF);
#pragma unroll
            for (int h = 0; h < 2; h++) {
                const uint32_t d = tmem_base + h * 256u;
                const uint64_t adh = ad + h * 1024;  // +128 rows * 128B = 16KB = 1024 units
#pragma unroll
                for (int k = 0; k < 4; k++) {
                    const uint32_t en = (i == 0 && k == 0) ? 0u : 1u;
                    mma_f16_ss(d, adh + k * 2, bd + k * 2, MMA_IDESC, en);
                }
            }
            TC_COMMIT(mb_empty + slot * 8);
            if (i == 15 || i == 31 || i == 47) TC_COMMIT(mb_chunk);
            if (i == NITER - 1) TC_COMMIT(mb_final);
        }

        // produce stage i+2 once its slot (occupant i-1) is recycled
        if (i < NITER - (STAGES - 1)) {
            const int t = i + STAGES - 1;
            if (t >= STAGES)
                mbar_wait(mb_empty + (t % STAGES) * 8, (uint32_t)(((t / STAGES) - 1) & 1));
            produce(t);
            CPA_COMMIT;
        }
    }

    // epilogue: each half -> 128 rows x 256 cols
    mbar_wait(mb_final, 0u);
    TC_FENCE_AFTER();
    if (tid < 128) {
        const float fs = cs[3];
        const float* brow = bias + bn * BT;
#pragma unroll
        for (int h = 0; h < 2; h++) {
            const int row = bm * BT + h * 128 + tid;
            float* orow = out + (size_t)row * N_DIM + bn * BT;
#pragma unroll
            for (int nb = 0; nb < 8; nb++) {
                uint32_t a[32];
                TC_LD32(a, tmem_base + h * 256 + nb * 32);
                TC_WAIT_LD();
#pragma unroll
                for (int j = 0; j < 32; j += 4) {
                    float4 bb = *(const float4*)(brow + nb * 32 + j);
                    float4 v;
                    v.x = __uint_as_float(a[j + 0]) * fs + bb.x;
                    v.y = __uint_as_float(a[j + 1]) * fs + bb.y;
                    v.z = __uint_as_float(a[j + 2]) * fs + bb.z;
                    v.w = __uint_as_float(a[j + 3]) * fs + bb.w;
                    *(float4*)(orow + nb * 32 + j) = v;
                }
            }
        }
        TC_FENCE_BEFORE();
    }
    __syncthreads();
    if (tid == 0) { MBAR_INVAL(mb_chunk); MBAR_INVAL(mb_final); }
    if (warp == 0) TC_DEALLOC(tmem_base, 512);
#endif  // HAS_TC
}

// ===========================================================================
// PATH 2: fallback mma.sync bf16 GEMM (active only when no tcgen05 in pass)
// ===========================================================================
#define FBM 128
#define FBN 128
#define FBK 32
#define FSTR 40

__device__ __forceinline__ void mma16816(float* c, const uint32_t* a, const uint32_t* b) {
    asm volatile(
        "mma.sync.aligned.m16n8k16.row.col.f32.bf16.bf16.f32 "
        "{%0,%1,%2,%3}, {%4,%5,%6,%7}, {%8,%9}, {%0,%1,%2,%3};\n"
        : "+f"(c[0]), "+f"(c[1]), "+f"(c[2]), "+f"(c[3])
        : "r"(a[0]), "r"(a[1]), "r"(a[2]), "r"(a[3]), "r"(b[0]), "r"(b[1]));
}

__global__ void __launch_bounds__(256) gemm_fb_kernel(const float* __restrict__ bias,
                                                      float* __restrict__ out) {
#if !HAS_TC
    __shared__ __nv_bfloat16 As[2][FBM * FSTR];
    __shared__ __nv_bfloat16 Bs[2][FBN * FSTR];

    const int bn = blockIdx.x, bm = blockIdx.y;
    const int tid = threadIdx.x;
    const int lane = tid & 31, warp = tid >> 5;
    const int g = lane >> 2, t4 = lane & 3;
    const int wm = (warp & 1) * 64;
    const int wn = (warp >> 1) * 32;

    float cs[NCHUNK];
    {
        float sw = quant_scale(4);
#pragma unroll
        for (int c = 0; c < NCHUNK; c++) cs[c] = quant_scale(c) * sw;
    }

    const int r = tid >> 1, kc = (tid & 1) * 16;
    const __nv_bfloat16* gA = g_qx + (size_t)(bm * FBM + r) * K_DIM + kc;
    const __nv_bfloat16* gB = g_qw + (size_t)(bn * FBN + r) * K_DIM + kc;

    auto cpa = [&](void* sdst, const void* gsrc) {
        unsigned sa = (unsigned)__cvta_generic_to_shared(sdst);
        asm volatile("cp.async.cg.shared.global [%0], [%1], 16;\n" :: "r"(sa), "l"(gsrc));
    };
    auto issue = [&](int stage) {
        int buf = stage & 1;
        int kt = stage * FBK;
        cpa(&As[buf][r * FSTR + kc],     gA + kt);
        cpa(&As[buf][r * FSTR + kc + 8], gA + kt + 8);
        cpa(&Bs[buf][r * FSTR + kc],     gB + kt);
        cpa(&Bs[buf][r * FSTR + kc + 8], gB + kt + 8);
    };

    float acc[4][4][4];
#pragma unroll
    for (int mt = 0; mt < 4; mt++)
#pragma unroll
        for (int nt = 0; nt < 4; nt++)
#pragma unroll
            for (int i = 0; i < 4; i++) acc[mt][nt][i] = 0.f;

    const int NIT = K_DIM / FBK;
    issue(0);
    CPA_COMMIT;

    for (int it = 0; it < NIT; ++it) {
        if (it + 1 < NIT) {
            issue(it + 1);
            CPA_COMMIT;
            CPA_WAIT(1);
        } else {
            CPA_WAIT(0);
        }
        __syncthreads();

        const __nv_bfloat16* sa = As[it & 1];
        const __nv_bfloat16* sb = Bs[it & 1];
#pragma unroll
        for (int kk = 0; kk < FBK; kk += 16) {
            uint32_t af[4][4], bfr[4][2];
#pragma unroll
            for (int mt = 0; mt < 4; mt++) {
                const __nv_bfloat16* p = sa + (wm + mt * 16 + g) * FSTR + kk + t4 * 2;
                af[mt][0] = *(const uint32_t*)p;
                af[mt][1] = *(const uint32_t*)(p + 8 * FSTR);
                af[mt][2] = *(const uint32_t*)(p + 8);
                af[mt][3] = *(const uint32_t*)(p + 8 * FSTR + 8);
            }
#pragma unroll
            for (int nt = 0; nt < 4; nt++) {
                const __nv_bfloat16* p = sb + (wn + nt * 8 + g) * FSTR + kk + t4 * 2;
                bfr[nt][0] = *(const uint32_t*)p;
                bfr[nt][1] = *(const uint32_t*)(p + 8);
            }
#pragma unroll
            for (int mt = 0; mt < 4; mt++)
#pragma unroll
                for (int nt = 0; nt < 4; nt++)
                    mma16816(acc[mt][nt], af[mt], bfr[nt]);
        }
        __syncthreads();

        if (((it + 1) & 31) == 0 && (it + 1) < NIT) {
            int c = ((it + 1) >> 5) - 1;
            float rt = cs[c] / cs[c + 1];
#pragma unroll
            for (int mt = 0; mt < 4; mt++)
#pragma unroll
                for (int nt = 0; nt < 4; nt++)
#pragma unroll
                    for (int i = 0; i < 4; i++) acc[mt][nt][i] *= rt;
        }
    }

    const float fs = cs[3];
#pragma unroll
    for (int mt = 0; mt < 4; mt++) {
        int row0 = bm * FBM + wm + mt * 16 + g;
#pragma unroll
        for (int nt = 0; nt < 4; nt++) {
            int col = bn * FBN + wn + nt * 8 + t4 * 2;
            float b0 = bias[col], b1 = bias[col + 1];
            float2 v0 = make_float2(acc[mt][nt][0] * fs + b0, acc[mt][nt][1] * fs + b1);
            float2 v1 = make_float2(acc[mt][nt][2] * fs + b0, acc[mt][nt][3] * fs + b1);
            *(float2*)(out + (size_t)row0 * N_DIM + col) = v0;
            *(float2*)(out + (size_t)(row0 + 8) * N_DIM + col) = v1;
        }
    }
#endif  // !HAS_TC
}

// ---------------------------------------------------------------------------
extern "C" void kernel_launch(void* const* d_in, const int* in_sizes, int n_in,
                              void* d_out, int out_size) {
    const float* x = (const float*)d_in[0];
    const float* w = (const float*)d_in[1];
    const float* bias = (const float*)d_in[2];
    float* out = (float*)d_out;

    const int nx = M_DIM * K_DIM;
    const int nw = N_DIM * K_DIM;

    zero_kernel<<<1, 32>>>();
    absmax_kernel<<<1024, 256>>>(x, nx, 0);
    absmax_kernel<<<512, 256>>>(w, nw, 1);
    quant_x_kernel<<<8192, 256>>>(x, nx);
    quant_w_kernel<<<2048, 256>>>(w, nw);

    cudaFuncSetAttribute(gemm_tc_kernel,
                         cudaFuncAttributeMaxDynamicSharedMemorySize, SMEM_TOTAL);
    dim3 gtc(N_DIM / BT, M_DIM / BT);   // (16, 64) = 1024 CTAs
    gemm_tc_kernel<<<gtc, 256, SMEM_TOTAL>>>(bias, out);

    dim3 gfb(N_DIM / FBN, M_DIM / FBM);
    gemm_fb_kernel<<<gfb, 256>>>(bias, out);
}

// round 7
// speedup vs baseline: 1.4155x; 1.0468x over previous
#include <cuda_runtime.h>
#include <cuda_bf16.h>
#include <cstdint>

#define M_DIM 16384
#define N_DIM 4096
#define K_DIM 4096
#define NCHUNK 4

#if defined(__CUDA_ARCH__) && (defined(__CUDA_ARCH_FEAT_SM103_ALL) || defined(__CUDA_ARCH_FEAT_SM100_ALL) || defined(__CUDA_ARCH_FEAT_SM101_ALL))
#define HAS_TC 1
#else
#define HAS_TC 0
#endif

// Scratch
__device__ __nv_bfloat16 g_qx[(size_t)M_DIM * K_DIM];
__device__ __nv_bfloat16 g_qw[(size_t)N_DIM * K_DIM];
__device__ unsigned g_absmax_bits[8];

#define NX (M_DIM * K_DIM)     // 67108864
#define NW (N_DIM * K_DIM)     // 16777216
#define ABS_X_BLOCKS 1024
#define ABS_W_BLOCKS 512
#define QNT_X_BLOCKS 8192
#define QNT_W_BLOCKS 2048

// ---------------------------------------------------------------------------
__global__ void zero_kernel() {
    if (threadIdx.x < 8) g_absmax_bits[threadIdx.x] = 0u;
}

// merged absmax: blocks [0, ABS_X_BLOCKS) -> x (per-chunk), rest -> w
__global__ void absmax_kernel(const float* __restrict__ x, const float* __restrict__ w) {
    __shared__ unsigned smax[5];
    if (threadIdx.x < 5) smax[threadIdx.x] = 0u;
    __syncthreads();

    const int is_w = blockIdx.x >= ABS_X_BLOCKS;
    const float* src = is_w ? w : x;
    const int n = is_w ? NW : NX;
    const int nblk = is_w ? ABS_W_BLOCKS : ABS_X_BLOCKS;
    const int bid = is_w ? (blockIdx.x - ABS_X_BLOCKS) : blockIdx.x;

    size_t stride = (size_t)nblk * blockDim.x * 4;
    size_t base = ((size_t)bid * blockDim.x + threadIdx.x) * 4;
    int c = is_w ? 4 : (int)((base & 4095) >> 10);
    float m = 0.f;
    for (size_t e = base; e < (size_t)n; e += stride) {
        float4 v = *(const float4*)(src + e);
        m = fmaxf(m, fmaxf(fmaxf(fabsf(v.x), fabsf(v.y)),
                           fmaxf(fabsf(v.z), fabsf(v.w))));
    }
    atomicMax(&smax[c], __float_as_uint(m));
    __syncthreads();
    if (threadIdx.x < 5) atomicMax(&g_absmax_bits[threadIdx.x], smax[threadIdx.x]);
}

__device__ __forceinline__ float quant_scale(int slot) {
    return fmaxf(__uint_as_float(g_absmax_bits[slot]) * (1.0f / 127.0f), 1e-8f);
}

// merged quant: blocks [0, QNT_X_BLOCKS) -> x, rest -> w
__global__ void quant_kernel(const float* __restrict__ x, const float* __restrict__ w) {
    const int is_w = blockIdx.x >= QNT_X_BLOCKS;
    float inv[NCHUNK];
    if (is_w) {
        float iw = 1.0f / quant_scale(4);
#pragma unroll
        for (int c = 0; c < NCHUNK; c++) inv[c] = iw;
    } else {
#pragma unroll
        for (int c = 0; c < NCHUNK; c++) inv[c] = 1.0f / quant_scale(c);
    }
    const float* src = is_w ? w : x;
    __nv_bfloat16* dst = is_w ? g_qw : g_qx;
    const int n = is_w ? NW : NX;
    const int nblk = is_w ? QNT_W_BLOCKS : QNT_X_BLOCKS;
    const int bid = is_w ? (blockIdx.x - QNT_X_BLOCKS) : blockIdx.x;

    size_t stride = (size_t)nblk * blockDim.x * 4;
    size_t base = ((size_t)bid * blockDim.x + threadIdx.x) * 4;
    for (size_t e = base; e < (size_t)n; e += stride) {
        int c = (int)((e & 4095) >> 10);
        float4 v = *(const float4*)(src + e);
        float q0 = fminf(fmaxf(rintf(v.x * inv[c]), -127.f), 127.f);
        float q1 = fminf(fmaxf(rintf(v.y * inv[c]), -127.f), 127.f);
        float q2 = fminf(fmaxf(rintf(v.z * inv[c]), -127.f), 127.f);
        float q3 = fminf(fmaxf(rintf(v.w * inv[c]), -127.f), 127.f);
        __nv_bfloat162 p0, p1;
        p0.x = __float2bfloat16_rn(q0); p0.y = __float2bfloat16_rn(q1);
        p1.x = __float2bfloat16_rn(q2); p1.y = __float2bfloat16_rn(q3);
        *(__nv_bfloat162*)(&dst[e])     = p0;
        *(__nv_bfloat162*)(&dst[e + 2]) = p1;
    }
}

// ===========================================================================
// cg1 tcgen05 GEMM, 256x256 CTA tile (two M=128 halves -> TMEM cols 0/256).
// K staged 64 deep, 3 stages x 64KB.
// ===========================================================================
#define BT 256
#define SK 64
#define STAGES 3
#define NITER (K_DIM / SK)            // 64
#define A_STAGE_BYTES (256 * 128)     // 32KB
#define B_STAGE_BYTES (256 * 128)     // 32KB
#define STAGE_BYTES (A_STAGE_BYTES + B_STAGE_BYTES)  // 64KB
#define SMEM_STAGE0 1024
#define SMEM_TOTAL (SMEM_STAGE0 + STAGES * STAGE_BYTES)  // 197632

#define MMA_IDESC ((8u << 24) | (32u << 17) | (1u << 10) | (1u << 7) | (1u << 4))

static constexpr uint64_t DESC_BASE_SW128 =
    (uint64_t(2) << 61) | (uint64_t(1) << 46) | (uint64_t(64) << 32) | (uint64_t(1) << 16);

__device__ __forceinline__ uint32_t smem_u32(const void* p) {
    return (uint32_t)__cvta_generic_to_shared(p);
}
__device__ __forceinline__ uint32_t swz(uint32_t o) { return o ^ ((o >> 3) & 0x70); }

__device__ __forceinline__ void cp16(uint32_t sdst, const void* gsrc) {
    asm volatile("cp.async.cg.shared.global [%0], [%1], 16;\n" :: "r"(sdst), "l"(gsrc));
}
#define CPA_COMMIT asm volatile("cp.async.commit_group;\n" ::: "memory")
#define CPA_WAIT(N) asm volatile("cp.async.wait_group %0;\n" :: "n"(N) : "memory")

#define MBAR_INIT(a, n) asm volatile("mbarrier.init.shared.b64 [%0], %1;" :: "r"(a), "r"(n) : "memory")
#define MBAR_INVAL(a)   asm volatile("mbarrier.inval.shared.b64 [%0];" :: "r"(a) : "memory")

__device__ __forceinline__ void mbar_wait(uint32_t addr, uint32_t parity) {
    asm volatile(
        "{\n\t.reg .pred P;\n\t"
        "WAIT_%=:\n\t"
        "mbarrier.try_wait.parity.acquire.cta.shared::cta.b64 P, [%0], %1, 0x989680;\n\t"
        "@P bra.uni DONE_%=;\n\t"
        "bra.uni WAIT_%=;\n\t"
        "DONE_%=:\n\t}"
        :: "r"(addr), "r"(parity) : "memory");
}

#if HAS_TC
#define TC_ALLOC(sp, n)   asm volatile("tcgen05.alloc.cta_group::1.sync.aligned.shared::cta.b32 [%0], %1;" :: "r"(sp), "r"(n) : "memory")
#define TC_DEALLOC(t, n)  asm volatile("tcgen05.dealloc.cta_group::1.sync.aligned.b32 %0, %1;" :: "r"(t), "r"(n))
#define TC_RELINQ()       asm volatile("tcgen05.relinquish_alloc_permit.cta_group::1.sync.aligned;")
#define TC_COMMIT(mb)     asm volatile("tcgen05.commit.cta_group::1.mbarrier::arrive::one.shared::cluster.b64 [%0];" :: "r"(mb) : "memory")
#define TC_WAIT_LD()      asm volatile("tcgen05.wait::ld.sync.aligned;" ::: "memory")
#define TC_WAIT_ST()      asm volatile("tcgen05.wait::st.sync.aligned;" ::: "memory")
#define TC_FENCE_BEFORE() asm volatile("tcgen05.fence::before_thread_sync;" ::: "memory")
#define TC_FENCE_AFTER()  asm volatile("tcgen05.fence::after_thread_sync;" ::: "memory")
#define FENCE_ASYNC()     asm volatile("fence.proxy.async.shared::cta;" ::: "memory")

__device__ __forceinline__ void mma_f16_ss(uint32_t d, uint64_t ad, uint64_t bd,
                                           uint32_t idesc, uint32_t en) {
    asm volatile(
        "{\n\t.reg .pred p;\n\t"
        "setp.ne.u32 p, %4, 0;\n\t"
        "tcgen05.mma.cta_group::1.kind::f16 [%0], %1, %2, %3, {%5,%5,%5,%5}, p;\n\t}"
        :: "r"(d), "l"(ad), "l"(bd), "r"(idesc), "r"(en), "r"(0u) : "memory");
}

#define TC_LD32(r, addr) \
    asm volatile( \
        "tcgen05.ld.sync.aligned.32x32b.x32.b32 " \
        "{%0,%1,%2,%3,%4,%5,%6,%7,%8,%9,%10,%11,%12,%13,%14,%15," \
        "%16,%17,%18,%19,%20,%21,%22,%23,%24,%25,%26,%27,%28,%29,%30,%31}, [%32];" \
        : "=r"((r)[0]),"=r"((r)[1]),"=r"((r)[2]),"=r"((r)[3]),"=r"((r)[4]),"=r"((r)[5]),"=r"((r)[6]),"=r"((r)[7]), \
          "=r"((r)[8]),"=r"((r)[9]),"=r"((r)[10]),"=r"((r)[11]),"=r"((r)[12]),"=r"((r)[13]),"=r"((r)[14]),"=r"((r)[15]), \
          "=r"((r)[16]),"=r"((r)[17]),"=r"((r)[18]),"=r"((r)[19]),"=r"((r)[20]),"=r"((r)[21]),"=r"((r)[22]),"=r"((r)[23]), \
          "=r"((r)[24]),"=r"((r)[25]),"=r"((r)[26]),"=r"((r)[27]),"=r"((r)[28]),"=r"((r)[29]),"=r"((r)[30]),"=r"((r)[31]) \
        : "r"(addr))

#define TC_ST32(addr, r) \
    asm volatile( \
        "tcgen05.st.sync.aligned.32x32b.x32.b32 [%0], " \
        "{%1,%2,%3,%4,%5,%6,%7,%8,%9,%10,%11,%12,%13,%14,%15,%16," \
        "%17,%18,%19,%20,%21,%22,%23,%24,%25,%26,%27,%28,%29,%30,%31,%32};" \
        :: "r"(addr), \
           "r"((r)[0]),"r"((r)[1]),"r"((r)[2]),"r"((r)[3]),"r"((r)[4]),"r"((r)[5]),"r"((r)[6]),"r"((r)[7]), \
           "r"((r)[8]),"r"((r)[9]),"r"((r)[10]),"r"((r)[11]),"r"((r)[12]),"r"((r)[13]),"r"((r)[14]),"r"((r)[15]), \
           "r"((r)[16]),"r"((r)[17]),"r"((r)[18]),"r"((r)[19]),"r"((r)[20]),"r"((r)[21]),"r"((r)[22]),"r"((r)[23]), \
           "r"((r)[24]),"r"((r)[25]),"r"((r)[26]),"r"((r)[27]),"r"((r)[28]),"r"((r)[29]),"r"((r)[30]),"r"((r)[31]) \
        : "memory")
#endif  // HAS_TC

__global__ void __launch_bounds__(256, 1) gemm_tc_kernel(const float* __restrict__ bias,
                                                         float* __restrict__ out) {
#if HAS_TC
    extern __shared__ char smem[];
    const uint32_t sbase = smem_u32(smem);
    const int tid = threadIdx.x;
    const int warp = tid >> 5;
    const int bn = blockIdx.x, bm = blockIdx.y;

    const uint32_t mb_empty = sbase + 16;   // [0..2]
    const uint32_t mb_chunk = sbase + 48;
    const uint32_t mb_final = sbase + 56;

    if (tid == 0) {
#pragma unroll
        for (int s = 0; s < STAGES; s++) MBAR_INIT(mb_empty + s * 8, 1);
        MBAR_INIT(mb_chunk, 1);
        MBAR_INIT(mb_final, 1);
    }
    if (warp == 0) { TC_ALLOC(sbase, 512); TC_RELINQ(); }
    __syncthreads();

    uint32_t tmem_base;
    asm volatile("ld.shared.b32 %0, [%1];" : "=r"(tmem_base) : "r"(sbase));

    float cs[NCHUNK];
    {
        float sw = quant_scale(4);
#pragma unroll
        for (int c = 0; c < NCHUNK; c++) cs[c] = quant_scale(c) * sw;
    }

    const __nv_bfloat16* gA = g_qx + (size_t)(bm * BT) * K_DIM;
    const __nv_bfloat16* gB = g_qw + (size_t)(bn * BT) * K_DIM;

    auto produce = [&](int t) {
        const int slot = t % STAGES;
        const uint32_t abase = sbase + SMEM_STAGE0 + slot * STAGE_BYTES;
        const uint32_t bbase = abase + A_STAGE_BYTES;
        const int kt = t * SK;
#pragma unroll
        for (int j = 0; j < 8; j++) {
            int ch = tid + j * 256;
            int row = ch >> 3, c16 = ch & 7;
            cp16(abase + swz(row * 128 + c16 * 16),
                 gA + (size_t)row * K_DIM + kt + c16 * 8);
        }
#pragma unroll
        for (int j = 0; j < 8; j++) {
            int ch = tid + j * 256;
            int row = ch >> 3, c16 = ch & 7;
            cp16(bbase + swz(row * 128 + c16 * 16),
                 gB + (size_t)row * K_DIM + kt + c16 * 8);
        }
    };

#pragma unroll
    for (int t = 0; t < STAGES - 1; t++) {
        produce(t);
        CPA_COMMIT;
    }

    for (int i = 0; i < NITER; ++i) {
        if (i <= NITER - 2) { CPA_WAIT(1); }
        else { CPA_WAIT(0); }
        __syncthreads();

        // chunk-boundary in-place rescale, pipelined: 4 col-blocks per wait
        if (i == 16 || i == 32 || i == 48) {
            if (tid < 128) {
                mbar_wait(mb_chunk, (uint32_t)(((i >> 4) - 1) & 1));
                TC_FENCE_AFTER();
                const float ratio = cs[(i >> 4) - 1] / cs[i >> 4];
                const uint32_t woff = (uint32_t)(tid >> 5) << 21;
#pragma unroll
                for (int g4 = 0; g4 < 4; g4++) {
                    uint32_t r[4][32];
#pragma unroll
                    for (int b = 0; b < 4; b++)
                        TC_LD32(r[b], tmem_base + (g4 * 4 + b) * 32);
                    TC_WAIT_LD();
#pragma unroll
                    for (int b = 0; b < 4; b++)
#pragma unroll
                        for (int j = 0; j < 32; j++)
                            r[b][j] = __float_as_uint(__uint_as_float(r[b][j]) * ratio);
#pragma unroll
                    for (int b = 0; b < 4; b++)
                        TC_ST32(tmem_base + (g4 * 4 + b) * 32 + woff, r[b]);
                    TC_WAIT_ST();
                }
                TC_FENCE_BEFORE();
            }
            __syncthreads();
        }

        // MMA issue (single thread): two M=128 halves
        if (tid == 0) {
            FENCE_ASYNC();
            if (i == 16 || i == 32 || i == 48) TC_FENCE_AFTER();
            const int slot = i % STAGES;
            const uint32_t abase = sbase + SMEM_STAGE0 + slot * STAGE_BYTES;
            const uint64_t ad = DESC_BASE_SW128 | ((uint64_t)(abase >> 4) & 0x3FFF);
            const uint64_t bd = DESC_BASE_SW128 | ((uint64_t)((abase + A_STAGE_BYTES) >> 4) & 0x3FFF);
#pragma unroll
            for (int h = 0; h < 2; h++) {
                const uint32_t d = tmem_base + h * 256u;
                const uint64_t adh = ad + h * 1024;
#pragma unroll
                for (int k = 0; k < 4; k++) {
                    const uint32_t en = (i == 0 && k == 0) ? 0u : 1u;
                    mma_f16_ss(d, adh + k * 2, bd + k * 2, MMA_IDESC, en);
                }
            }
            TC_COMMIT(mb_empty + slot * 8);
            if (i == 15 || i == 31 || i == 47) TC_COMMIT(mb_chunk);
            if (i == NITER - 1) TC_COMMIT(mb_final);
        }

        if (i < NITER - (STAGES - 1)) {
            const int t = i + STAGES - 1;
            if (t >= STAGES)
                mbar_wait(mb_empty + (t % STAGES) * 8, (uint32_t)(((t / STAGES) - 1) & 1));
            produce(t);
            CPA_COMMIT;
        }
    }

    // epilogue: two halves, 2 col-blocks per wait
    mbar_wait(mb_final, 0u);
    TC_FENCE_AFTER();
    if (tid < 128) {
        const float fs = cs[3];
        const float* brow = bias + bn * BT;
#pragma unroll
        for (int h = 0; h < 2; h++) {
            const int row = bm * BT + h * 128 + tid;
            float* orow = out + (size_t)row * N_DIM + bn * BT;
#pragma unroll
            for (int nb = 0; nb < 8; nb += 2) {
                uint32_t a0[32], a1[32];
                TC_LD32(a0, tmem_base + h * 256 + nb * 32);
                TC_LD32(a1, tmem_base + h * 256 + (nb + 1) * 32);
                TC_WAIT_LD();
#pragma unroll
                for (int j = 0; j < 32; j += 4) {
                    float4 bb = *(const float4*)(brow + nb * 32 + j);
                    float4 v;
                    v.x = __uint_as_float(a0[j + 0]) * fs + bb.x;
                    v.y = __uint_as_float(a0[j + 1]) * fs + bb.y;
                    v.z = __uint_as_float(a0[j + 2]) * fs + bb.z;
                    v.w = __uint_as_float(a0[j + 3]) * fs + bb.w;
                    *(float4*)(orow + nb * 32 + j) = v;
                }
#pragma unroll
                for (int j = 0; j < 32; j += 4) {
                    float4 bb = *(const float4*)(brow + (nb + 1) * 32 + j);
                    float4 v;
                    v.x = __uint_as_float(a1[j + 0]) * fs + bb.x;
                    v.y = __uint_as_float(a1[j + 1]) * fs + bb.y;
                    v.z = __uint_as_float(a1[j + 2]) * fs + bb.z;
                    v.w = __uint_as_float(a1[j + 3]) * fs + bb.w;
                    *(float4*)(orow + (nb + 1) * 32 + j) = v;
                }
            }
        }
        TC_FENCE_BEFORE();
    }
    __syncthreads();
    if (tid == 0) { MBAR_INVAL(mb_chunk); MBAR_INVAL(mb_final); }
    if (warp == 0) TC_DEALLOC(tmem_base, 512);
#endif  // HAS_TC
}

// ---------------------------------------------------------------------------
extern "C" void kernel_launch(void* const* d_in, const int* in_sizes, int n_in,
                              void* d_out, int out_size) {
    const float* x = (const float*)d_in[0];
    const float* w = (const float*)d_in[1];
    const float* bias = (const float*)d_in[2];
    float* out = (float*)d_out;

    zero_kernel<<<1, 32>>>();
    absmax_kernel<<<ABS_X_BLOCKS + ABS_W_BLOCKS, 256>>>(x, w);
    quant_kernel<<<QNT_X_BLOCKS + QNT_W_BLOCKS, 256>>>(x, w);

    cudaFuncSetAttribute(gemm_tc_kernel,
                         cudaFuncAttributeMaxDynamicSharedMemorySize, SMEM_TOTAL);
    dim3 gtc(N_DIM / BT, M_DIM / BT);   // (16, 64) = 1024 CTAs
    gemm_tc_kernel<<<gtc, 256, SMEM_TOTAL>>>(bias, out);
}

// round 10
// speedup vs baseline: 1.4468x; 1.0221x over previous
#include <cuda_runtime.h>
#include <cuda_bf16.h>
#include <cstdint>

#define M_DIM 16384
#define N_DIM 4096
#define K_DIM 4096
#define NCHUNK 4

#if defined(__CUDA_ARCH__) && (defined(__CUDA_ARCH_FEAT_SM103_ALL) || defined(__CUDA_ARCH_FEAT_SM100_ALL) || defined(__CUDA_ARCH_FEAT_SM101_ALL))
#define HAS_TC 1
#else
#define HAS_TC 0
#endif

// Scratch
__device__ __nv_bfloat16 g_qx[(size_t)M_DIM * K_DIM];
__device__ __nv_bfloat16 g_qw[(size_t)N_DIM * K_DIM];
__device__ unsigned g_absmax_bits[8];

#define NX (M_DIM * K_DIM)
#define NW (N_DIM * K_DIM)
#define ABS_X_BLOCKS 1024
#define ABS_W_BLOCKS 512
#define QNT_X_BLOCKS 8192
#define QNT_W_BLOCKS 2048

// ---------------------------------------------------------------------------
__global__ void zero_kernel() {
    if (threadIdx.x < 8) g_absmax_bits[threadIdx.x] = 0u;
}

__global__ void absmax_kernel(const float* __restrict__ x, const float* __restrict__ w) {
    __shared__ unsigned smax[5];
    if (threadIdx.x < 5) smax[threadIdx.x] = 0u;
    __syncthreads();

    const int is_w = blockIdx.x >= ABS_X_BLOCKS;
    const float* src = is_w ? w : x;
    const int n = is_w ? NW : NX;
    const int nblk = is_w ? ABS_W_BLOCKS : ABS_X_BLOCKS;
    const int bid = is_w ? (blockIdx.x - ABS_X_BLOCKS) : blockIdx.x;

    size_t stride = (size_t)nblk * blockDim.x * 4;
    size_t base = ((size_t)bid * blockDim.x + threadIdx.x) * 4;
    int c = is_w ? 4 : (int)((base & 4095) >> 10);
    float m = 0.f;
    for (size_t e = base; e < (size_t)n; e += stride) {
        float4 v = *(const float4*)(src + e);
        m = fmaxf(m, fmaxf(fmaxf(fabsf(v.x), fabsf(v.y)),
                           fmaxf(fabsf(v.z), fabsf(v.w))));
    }
    atomicMax(&smax[c], __float_as_uint(m));
    __syncthreads();
    if (threadIdx.x < 5) atomicMax(&g_absmax_bits[threadIdx.x], smax[threadIdx.x]);
}

__device__ __forceinline__ float quant_scale(int slot) {
    return fmaxf(__uint_as_float(g_absmax_bits[slot]) * (1.0f / 127.0f), 1e-8f);
}

__global__ void quant_kernel(const float* __restrict__ x, const float* __restrict__ w) {
    const int is_w = blockIdx.x >= QNT_X_BLOCKS;
    float inv[NCHUNK];
    if (is_w) {
        float iw = 1.0f / quant_scale(4);
#pragma unroll
        for (int c = 0; c < NCHUNK; c++) inv[c] = iw;
    } else {
#pragma unroll
        for (int c = 0; c < NCHUNK; c++) inv[c] = 1.0f / quant_scale(c);
    }
    const float* src = is_w ? w : x;
    __nv_bfloat16* dst = is_w ? g_qw : g_qx;
    const int n = is_w ? NW : NX;
    const int nblk = is_w ? QNT_W_BLOCKS : QNT_X_BLOCKS;
    const int bid = is_w ? (blockIdx.x - QNT_X_BLOCKS) : blockIdx.x;

    size_t stride = (size_t)nblk * blockDim.x * 4;
    size_t base = ((size_t)bid * blockDim.x + threadIdx.x) * 4;
    for (size_t e = base; e < (size_t)n; e += stride) {
        int c = (int)((e & 4095) >> 10);
        float4 v = *(const float4*)(src + e);
        float q0 = fminf(fmaxf(rintf(v.x * inv[c]), -127.f), 127.f);
        float q1 = fminf(fmaxf(rintf(v.y * inv[c]), -127.f), 127.f);
        float q2 = fminf(fmaxf(rintf(v.z * inv[c]), -127.f), 127.f);
        float q3 = fminf(fmaxf(rintf(v.w * inv[c]), -127.f), 127.f);
        __nv_bfloat162 p0, p1;
        p0.x = __float2bfloat16_rn(q0); p0.y = __float2bfloat16_rn(q1);
        p1.x = __float2bfloat16_rn(q2); p1.y = __float2bfloat16_rn(q3);
        *(__nv_bfloat162*)(&dst[e])     = p0;
        *(__nv_bfloat162*)(&dst[e + 2]) = p1;
    }
}

// ===========================================================================
// Warp-specialized cg1 tcgen05 GEMM, 256x256 tile, 3 stages x 64KB.
// 384 threads: tid<256 producers (cp.async + noinc mbarrier arrive).
// tid 256-383 consumer warpgroup: warp 8 (all lanes, elect-one issue) drives
// MMAs; all 4 consumer warps do TMEM rescale + epilogue.
// ===========================================================================
#define BT 256
#define SK 64
#define STAGES 3
#define NITER (K_DIM / SK)            // 64
#define A_STAGE_BYTES (256 * 128)     // 32KB
#define B_STAGE_BYTES (256 * 128)     // 32KB
#define STAGE_BYTES (A_STAGE_BYTES + B_STAGE_BYTES)
#define SMEM_STAGE0 1024
#define SMEM_TOTAL (SMEM_STAGE0 + STAGES * STAGE_BYTES)  // 197632

#define MMA_IDESC ((8u << 24) | (32u << 17) | (1u << 10) | (1u << 7) | (1u << 4))

static constexpr uint64_t DESC_BASE_SW128 =
    (uint64_t(2) << 61) | (uint64_t(1) << 46) | (uint64_t(64) << 32) | (uint64_t(1) << 16);

__device__ __forceinline__ uint32_t smem_u32(const void* p) {
    return (uint32_t)__cvta_generic_to_shared(p);
}
__device__ __forceinline__ uint32_t swz(uint32_t o) { return o ^ ((o >> 3) & 0x70); }

__device__ __forceinline__ void cp16(uint32_t sdst, const void* gsrc) {
    asm volatile("cp.async.cg.shared.global [%0], [%1], 16;\n" :: "r"(sdst), "l"(gsrc));
}
// CRITICAL: .noinc — default variant pre-increments pending count and the
// deferred arrive nets to zero, so the barrier would never flip (R8/R9 hang).
#define CPA_ARRIVE(mb) asm volatile("cp.async.mbarrier.arrive.noinc.shared::cta.b64 [%0];" :: "r"(mb) : "memory")

#define MBAR_INIT(a, n) asm volatile("mbarrier.init.shared.b64 [%0], %1;" :: "r"(a), "r"(n) : "memory")
#define MBAR_INVAL(a)   asm volatile("mbarrier.inval.shared.b64 [%0];" :: "r"(a) : "memory")

__device__ __forceinline__ void mbar_wait(uint32_t addr, uint32_t parity) {
    asm volatile(
        "{\n\t.reg .pred P;\n\t"
        "WAIT_%=:\n\t"
        "mbarrier.try_wait.parity.acquire.cta.shared::cta.b64 P, [%0], %1, 0x989680;\n\t"
        "@P bra.uni DONE_%=;\n\t"
        "bra.uni WAIT_%=;\n\t"
        "DONE_%=:\n\t}"
        :: "r"(addr), "r"(parity) : "memory");
}

__device__ __forceinline__ bool elect1() {
    uint32_t r;
    asm volatile(
        "{\n\t.reg .pred p;\n\t"
        "elect.sync _|p, 0xFFFFFFFF;\n\t"
        "selp.b32 %0, 1, 0, p;\n\t}"
        : "=r"(r));
    return r != 0;
}

#if HAS_TC
#define TC_ALLOC(sp, n)   asm volatile("tcgen05.alloc.cta_group::1.sync.aligned.shared::cta.b32 [%0], %1;" :: "r"(sp), "r"(n) : "memory")
#define TC_DEALLOC(t, n)  asm volatile("tcgen05.dealloc.cta_group::1.sync.aligned.b32 %0, %1;" :: "r"(t), "r"(n))
#define TC_RELINQ()       asm volatile("tcgen05.relinquish_alloc_permit.cta_group::1.sync.aligned;")
#define TC_COMMIT(mb)     asm volatile("tcgen05.commit.cta_group::1.mbarrier::arrive::one.shared::cluster.b64 [%0];" :: "r"(mb) : "memory")
#define TC_WAIT_LD()      asm volatile("tcgen05.wait::ld.sync.aligned;" ::: "memory")
#define TC_WAIT_ST()      asm volatile("tcgen05.wait::st.sync.aligned;" ::: "memory")
#define TC_FENCE_BEFORE() asm volatile("tcgen05.fence::before_thread_sync;" ::: "memory")
#define TC_FENCE_AFTER()  asm volatile("tcgen05.fence::after_thread_sync;" ::: "memory")
#define FENCE_ASYNC()     asm volatile("fence.proxy.async.shared::cta;" ::: "memory")
#define NAMED_BAR(id, n)  asm volatile("bar.sync %0, %1;" :: "r"(id), "r"(n) : "memory")

__device__ __forceinline__ void mma_f16_ss(uint32_t d, uint64_t ad, uint64_t bd,
                                           uint32_t idesc, uint32_t en) {
    asm volatile(
        "{\n\t.reg .pred p;\n\t"
        "setp.ne.u32 p, %4, 0;\n\t"
        "tcgen05.mma.cta_group::1.kind::f16 [%0], %1, %2, %3, {%5,%5,%5,%5}, p;\n\t}"
        :: "r"(d), "l"(ad), "l"(bd), "r"(idesc), "r"(en), "r"(0u) : "memory");
}

#define TC_LD32(r, addr) \
    asm volatile( \
        "tcgen05.ld.sync.aligned.32x32b.x32.b32 " \
        "{%0,%1,%2,%3,%4,%5,%6,%7,%8,%9,%10,%11,%12,%13,%14,%15," \
        "%16,%17,%18,%19,%20,%21,%22,%23,%24,%25,%26,%27,%28,%29,%30,%31}, [%32];" \
        : "=r"((r)[0]),"=r"((r)[1]),"=r"((r)[2]),"=r"((r)[3]),"=r"((r)[4]),"=r"((r)[5]),"=r"((r)[6]),"=r"((r)[7]), \
          "=r"((r)[8]),"=r"((r)[9]),"=r"((r)[10]),"=r"((r)[11]),"=r"((r)[12]),"=r"((r)[13]),"=r"((r)[14]),"=r"((r)[15]), \
          "=r"((r)[16]),"=r"((r)[17]),"=r"((r)[18]),"=r"((r)[19]),"=r"((r)[20]),"=r"((r)[21]),"=r"((r)[22]),"=r"((r)[23]), \
          "=r"((r)[24]),"=r"((r)[25]),"=r"((r)[26]),"=r"((r)[27]),"=r"((r)[28]),"=r"((r)[29]),"=r"((r)[30]),"=r"((r)[31]) \
        : "r"(addr))

#define TC_ST32(addr, r) \
    asm volatile( \
        "tcgen05.st.sync.aligned.32x32b.x32.b32 [%0], " \
        "{%1,%2,%3,%4,%5,%6,%7,%8,%9,%10,%11,%12,%13,%14,%15,%16," \
        "%17,%18,%19,%20,%21,%22,%23,%24,%25,%26,%27,%28,%29,%30,%31,%32};" \
        :: "r"(addr), \
           "r"((r)[0]),"r"((r)[1]),"r"((r)[2]),"r"((r)[3]),"r"((r)[4]),"r"((r)[5]),"r"((r)[6]),"r"((r)[7]), \
           "r"((r)[8]),"r"((r)[9]),"r"((r)[10]),"r"((r)[11]),"r"((r)[12]),"r"((r)[13]),"r"((r)[14]),"r"((r)[15]), \
           "r"((r)[16]),"r"((r)[17]),"r"((r)[18]),"r"((r)[19]),"r"((r)[20]),"r"((r)[21]),"r"((r)[22]),"r"((r)[23]), \
           "r"((r)[24]),"r"((r)[25]),"r"((r)[26]),"r"((r)[27]),"r"((r)[28]),"r"((r)[29]),"r"((r)[30]),"r"((r)[31]) \
        : "memory")
#endif  // HAS_TC

__global__ void __launch_bounds__(384, 1) gemm_tc_kernel(const float* __restrict__ bias,
                                                         float* __restrict__ out) {
#if HAS_TC
    extern __shared__ char smem[];
    const uint32_t sbase = smem_u32(smem);
    const int tid = threadIdx.x;
    const int bn = blockIdx.x, bm = blockIdx.y;

    const uint32_t mb_full  = sbase + 16;   // [0..2], count 256
    const uint32_t mb_empty = sbase + 40;   // [0..2], count 1
    const uint32_t mb_chunk = sbase + 64;
    const uint32_t mb_final = sbase + 72;

    if (tid == 0) {
#pragma unroll
        for (int s = 0; s < STAGES; s++) {
            MBAR_INIT(mb_full + s * 8, 256);
            MBAR_INIT(mb_empty + s * 8, 1);
        }
        MBAR_INIT(mb_chunk, 1);
        MBAR_INIT(mb_final, 1);
    }
    if (tid >= 256 && tid < 288) { TC_ALLOC(sbase, 512); TC_RELINQ(); }
    __syncthreads();

    uint32_t tmem_base;
    asm volatile("ld.shared.b32 %0, [%1];" : "=r"(tmem_base) : "r"(sbase));

    float cs[NCHUNK];
    {
        float sw = quant_scale(4);
#pragma unroll
        for (int c = 0; c < NCHUNK; c++) cs[c] = quant_scale(c) * sw;
    }

    if (tid < 256) {
        // ================= PRODUCERS =================
        const __nv_bfloat16* gA = g_qx + (size_t)(bm * BT) * K_DIM;
        const __nv_bfloat16* gB = g_qw + (size_t)(bn * BT) * K_DIM;
        for (int t = 0; t < NITER; ++t) {
            const int slot = t % STAGES;
            if (t >= STAGES)
                mbar_wait(mb_empty + slot * 8, (uint32_t)(((t / STAGES) - 1) & 1));
            const uint32_t abase = sbase + SMEM_STAGE0 + slot * STAGE_BYTES;
            const uint32_t bbase = abase + A_STAGE_BYTES;
            const int kt = t * SK;
#pragma unroll
            for (int j = 0; j < 8; j++) {
                int ch = tid + j * 256;
                int row = ch >> 3, c16 = ch & 7;
                cp16(abase + swz(row * 128 + c16 * 16),
                     gA + (size_t)row * K_DIM + kt + c16 * 8);
            }
#pragma unroll
            for (int j = 0; j < 8; j++) {
                int ch = tid + j * 256;
                int row = ch >> 3, c16 = ch & 7;
                cp16(bbase + swz(row * 128 + c16 * 16),
                     gB + (size_t)row * K_DIM + kt + c16 * 8);
            }
            CPA_ARRIVE(mb_full + slot * 8);
        }
    } else {
        // ================= CONSUMER WARPGROUP (128 threads) =================
        const int ctid = tid - 256;
        const int cwarp = ctid >> 5;
        const uint32_t cwoff = (uint32_t)cwarp << 21;

        // 4 chunk segments of 16 stages each; rescale between segments
        for (int seg = 0; seg < 4; ++seg) {
            if (cwarp == 0) {
                const int i0 = seg * 16;
#pragma unroll 1
                for (int i = i0; i < i0 + 16; ++i) {
                    const int slot = i % STAGES;
                    mbar_wait(mb_full + slot * 8, (uint32_t)((i / STAGES) & 1));
                    if (elect1()) {
                        FENCE_ASYNC();
                        const uint32_t abase = sbase + SMEM_STAGE0 + slot * STAGE_BYTES;
                        const uint64_t ad = DESC_BASE_SW128 | ((uint64_t)(abase >> 4) & 0x3FFF);
                        const uint64_t bd = DESC_BASE_SW128 | ((uint64_t)((abase + A_STAGE_BYTES) >> 4) & 0x3FFF);
#pragma unroll
                        for (int h = 0; h < 2; h++) {
                            const uint32_t d = tmem_base + h * 256u;
                            const uint64_t adh = ad + h * 1024;
#pragma unroll
                            for (int k = 0; k < 4; k++) {
                                const uint32_t en = (i == 0 && k == 0) ? 0u : 1u;
                                mma_f16_ss(d, adh + k * 2, bd + k * 2, MMA_IDESC, en);
                            }
                        }
                        TC_COMMIT(mb_empty + slot * 8);
                    }
                    __syncwarp();
                }
                if (elect1()) {
                    if (seg < 3) TC_COMMIT(mb_chunk);
                    else         TC_COMMIT(mb_final);
                }
                __syncwarp();
            }

            if (seg < 3) {
                // rescale: all 4 consumer warps, converged per warp
                mbar_wait(mb_chunk, (uint32_t)(seg & 1));
                TC_FENCE_AFTER();
                const float ratio = cs[seg] / cs[seg + 1];
#pragma unroll
                for (int g = 0; g < 8; g++) {
                    uint32_t r[2][32];
                    TC_LD32(r[0], tmem_base + (g * 2) * 32);
                    TC_LD32(r[1], tmem_base + (g * 2 + 1) * 32);
                    TC_WAIT_LD();
#pragma unroll
                    for (int b = 0; b < 2; b++)
#pragma unroll
                        for (int j = 0; j < 32; j++)
                            r[b][j] = __float_as_uint(__uint_as_float(r[b][j]) * ratio);
                    TC_ST32(tmem_base + (g * 2) * 32 + cwoff, r[0]);
                    TC_ST32(tmem_base + (g * 2 + 1) * 32 + cwoff, r[1]);
                    TC_WAIT_ST();
                }
                TC_FENCE_BEFORE();
                NAMED_BAR(1, 128);
                TC_FENCE_AFTER();
            }
        }

        // epilogue
        mbar_wait(mb_final, 0u);
        TC_FENCE_AFTER();
        {
            const float fs = cs[3];
            const float* brow = bias + bn * BT;
#pragma unroll
            for (int h = 0; h < 2; h++) {
                const int row = bm * BT + h * 128 + ctid;
                float* orow = out + (size_t)row * N_DIM + bn * BT;
#pragma unroll
                for (int nb = 0; nb < 8; nb += 2) {
                    uint32_t a0[32], a1[32];
                    TC_LD32(a0, tmem_base + h * 256 + nb * 32);
                    TC_LD32(a1, tmem_base + h * 256 + (nb + 1) * 32);
                    TC_WAIT_LD();
#pragma unroll
                    for (int j = 0; j < 32; j += 4) {
                        float4 bb = *(const float4*)(brow + nb * 32 + j);
                        float4 v;
                        v.x = __uint_as_float(a0[j + 0]) * fs + bb.x;
                        v.y = __uint_as_float(a0[j + 1]) * fs + bb.y;
                        v.z = __uint_as_float(a0[j + 2]) * fs + bb.z;
                        v.w = __uint_as_float(a0[j + 3]) * fs + bb.w;
                        *(float4*)(orow + nb * 32 + j) = v;
                    }
#pragma unroll
                    for (int j = 0; j < 32; j += 4) {
                        float4 bb = *(const float4*)(brow + (nb + 1) * 32 + j);
                        float4 v;
                        v.x = __uint_as_float(a1[j + 0]) * fs + bb.x;
                        v.y = __uint_as_float(a1[j + 1]) * fs + bb.y;
                        v.z = __uint_as_float(a1[j + 2]) * fs + bb.z;
                        v.w = __uint_as_float(a1[j + 3]) * fs + bb.w;
                        *(float4*)(orow + (nb + 1) * 32 + j) = v;
                    }
                }
            }
            TC_FENCE_BEFORE();
        }
        NAMED_BAR(1, 128);
        if (cwarp == 0) {
            TC_DEALLOC(tmem_base, 512);
            if (elect1()) { MBAR_INVAL(mb_chunk); MBAR_INVAL(mb_final); }
        }
    }
#endif  // HAS_TC
}

// ---------------------------------------------------------------------------
extern "C" void kernel_launch(void* const* d_in, const int* in_sizes, int n_in,
                              void* d_out, int out_size) {
    const float* x = (const float*)d_in[0];
    const float* w = (const float*)d_in[1];
    const float* bias = (const float*)d_in[2];
    float* out = (float*)d_out;

    zero_kernel<<<1, 32>>>();
    absmax_kernel<<<ABS_X_BLOCKS + ABS_W_BLOCKS, 256>>>(x, w);
    quant_kernel<<<QNT_X_BLOCKS + QNT_W_BLOCKS, 256>>>(x, w);

    cudaFuncSetAttribute(gemm_tc_kernel,
                         cudaFuncAttributeMaxDynamicSharedMemorySize, SMEM_TOTAL);
    dim3 gtc(N_DIM / BT, M_DIM / BT);   // (16, 64)
    gemm_tc_kernel<<<gtc, 384, SMEM_TOTAL>>>(bias, out);
}

// round 11
// speedup vs baseline: 1.4516x; 1.0033x over previous
#include <cuda_runtime.h>
#include <cuda_bf16.h>
#include <cstdint>

#define M_DIM 16384
#define N_DIM 4096
#define K_DIM 4096
#define NCHUNK 4

#if defined(__CUDA_ARCH__) && (defined(__CUDA_ARCH_FEAT_SM103_ALL) || defined(__CUDA_ARCH_FEAT_SM100_ALL) || defined(__CUDA_ARCH_FEAT_SM101_ALL))
#define HAS_TC 1
#else
#define HAS_TC 0
#endif

// Scratch
__device__ __nv_bfloat16 g_qx[(size_t)M_DIM * K_DIM];
__device__ __nv_bfloat16 g_qw[(size_t)N_DIM * K_DIM];
__device__ unsigned g_absmax_bits[8];

#define NX (M_DIM * K_DIM)
#define NW (N_DIM * K_DIM)
#define ABS_X_BLOCKS 1024
#define ABS_W_BLOCKS 512
#define QNT_X_BLOCKS 8192
#define QNT_W_BLOCKS 2048

// ---------------------------------------------------------------------------
__global__ void zero_kernel() {
    if (threadIdx.x < 8) g_absmax_bits[threadIdx.x] = 0u;
}

__global__ void absmax_kernel(const float* __restrict__ x, const float* __restrict__ w) {
    __shared__ unsigned smax[5];
    if (threadIdx.x < 5) smax[threadIdx.x] = 0u;
    __syncthreads();

    const int is_w = blockIdx.x >= ABS_X_BLOCKS;
    const float* src = is_w ? w : x;
    const int n = is_w ? NW : NX;
    const int nblk = is_w ? ABS_W_BLOCKS : ABS_X_BLOCKS;
    const int bid = is_w ? (blockIdx.x - ABS_X_BLOCKS) : blockIdx.x;

    size_t stride = (size_t)nblk * blockDim.x * 4;
    size_t base = ((size_t)bid * blockDim.x + threadIdx.x) * 4;
    int c = is_w ? 4 : (int)((base & 4095) >> 10);
    float m = 0.f;
    for (size_t e = base; e < (size_t)n; e += stride) {
        float4 v = *(const float4*)(src + e);
        m = fmaxf(m, fmaxf(fmaxf(fabsf(v.x), fabsf(v.y)),
                           fmaxf(fabsf(v.z), fabsf(v.w))));
    }
    atomicMax(&smax[c], __float_as_uint(m));
    __syncthreads();
    if (threadIdx.x < 5) atomicMax(&g_absmax_bits[threadIdx.x], smax[threadIdx.x]);
}

__device__ __forceinline__ float quant_scale(int slot) {
    return fmaxf(__uint_as_float(g_absmax_bits[slot]) * (1.0f / 127.0f), 1e-8f);
}

__global__ void quant_kernel(const float* __restrict__ x, const float* __restrict__ w) {
    const int is_w = blockIdx.x >= QNT_X_BLOCKS;
    float inv[NCHUNK];
    if (is_w) {
        float iw = 1.0f / quant_scale(4);
#pragma unroll
        for (int c = 0; c < NCHUNK; c++) inv[c] = iw;
    } else {
#pragma unroll
        for (int c = 0; c < NCHUNK; c++) inv[c] = 1.0f / quant_scale(c);
    }
    const float* src = is_w ? w : x;
    __nv_bfloat16* dst = is_w ? g_qw : g_qx;
    const int n = is_w ? NW : NX;
    const int nblk = is_w ? QNT_W_BLOCKS : QNT_X_BLOCKS;
    const int bid = is_w ? (blockIdx.x - QNT_X_BLOCKS) : blockIdx.x;

    size_t stride = (size_t)nblk * blockDim.x * 4;
    size_t base = ((size_t)bid * blockDim.x + threadIdx.x) * 4;
    for (size_t e = base; e < (size_t)n; e += stride) {
        int c = (int)((e & 4095) >> 10);
        float4 v = *(const float4*)(src + e);
        float q0 = fminf(fmaxf(rintf(v.x * inv[c]), -127.f), 127.f);
        float q1 = fminf(fmaxf(rintf(v.y * inv[c]), -127.f), 127.f);
        float q2 = fminf(fmaxf(rintf(v.z * inv[c]), -127.f), 127.f);
        float q3 = fminf(fmaxf(rintf(v.w * inv[c]), -127.f), 127.f);
        __nv_bfloat162 p0, p1;
        p0.x = __float2bfloat16_rn(q0); p0.y = __float2bfloat16_rn(q1);
        p1.x = __float2bfloat16_rn(q2); p1.y = __float2bfloat16_rn(q3);
        *(__nv_bfloat162*)(&dst[e])     = p0;
        *(__nv_bfloat162*)(&dst[e + 2]) = p1;
    }
}

// ===========================================================================
// Warp-specialized cg1 tcgen05 GEMM, 256x256 tile, 3 stages x 64KB.
// 384 threads: tid<256 producers (cp.async + noinc mbarrier arrive).
// tid 256-383 consumer warpgroup: warp 8 (all lanes, elect-one issue) drives
// MMAs; all 4 consumer warps do TMEM rescale + epilogue.
// ===========================================================================
#define BT 256
#define SK 64
#define STAGES 3
#define NITER (K_DIM / SK)            // 64
#define A_STAGE_BYTES (256 * 128)     // 32KB
#define B_STAGE_BYTES (256 * 128)     // 32KB
#define STAGE_BYTES (A_STAGE_BYTES + B_STAGE_BYTES)
#define SMEM_STAGE0 1024
#define SMEM_TOTAL (SMEM_STAGE0 + STAGES * STAGE_BYTES)  // 197632

#define MMA_IDESC ((8u << 24) | (32u << 17) | (1u << 10) | (1u << 7) | (1u << 4))

static constexpr uint64_t DESC_BASE_SW128 =
    (uint64_t(2) << 61) | (uint64_t(1) << 46) | (uint64_t(64) << 32) | (uint64_t(1) << 16);

__device__ __forceinline__ uint32_t smem_u32(const void* p) {
    return (uint32_t)__cvta_generic_to_shared(p);
}
__device__ __forceinline__ uint32_t swz(uint32_t o) { return o ^ ((o >> 3) & 0x70); }

__device__ __forceinline__ void cp16(uint32_t sdst, const void* gsrc) {
    asm volatile("cp.async.cg.shared.global [%0], [%1], 16;\n" :: "r"(sdst), "l"(gsrc));
}
// CRITICAL: .noinc — default variant pre-increments pending count and the
// deferred arrive nets to zero, so the barrier would never flip (R8/R9 hang).
#define CPA_ARRIVE(mb) asm volatile("cp.async.mbarrier.arrive.noinc.shared::cta.b64 [%0];" :: "r"(mb) : "memory")

#define MBAR_INIT(a, n) asm volatile("mbarrier.init.shared.b64 [%0], %1;" :: "r"(a), "r"(n) : "memory")
#define MBAR_INVAL(a)   asm volatile("mbarrier.inval.shared.b64 [%0];" :: "r"(a) : "memory")

__device__ __forceinline__ void mbar_wait(uint32_t addr, uint32_t parity) {
    asm volatile(
        "{\n\t.reg .pred P;\n\t"
        "WAIT_%=:\n\t"
        "mbarrier.try_wait.parity.acquire.cta.shared::cta.b64 P, [%0], %1, 0x989680;\n\t"
        "@P bra.uni DONE_%=;\n\t"
        "bra.uni WAIT_%=;\n\t"
        "DONE_%=:\n\t}"
        :: "r"(addr), "r"(parity) : "memory");
}

__device__ __forceinline__ bool elect1() {
    uint32_t r;
    asm volatile(
        "{\n\t.reg .pred p;\n\t"
        "elect.sync _|p, 0xFFFFFFFF;\n\t"
        "selp.b32 %0, 1, 0, p;\n\t}"
        : "=r"(r));
    return r != 0;
}

#if HAS_TC
#define TC_ALLOC(sp, n)   asm volatile("tcgen05.alloc.cta_group::1.sync.aligned.shared::cta.b32 [%0], %1;" :: "r"(sp), "r"(n) : "memory")
#define TC_DEALLOC(t, n)  asm volatile("tcgen05.dealloc.cta_group::1.sync.aligned.b32 %0, %1;" :: "r"(t), "r"(n))
#define TC_RELINQ()       asm volatile("tcgen05.relinquish_alloc_permit.cta_group::1.sync.aligned;")
#define TC_COMMIT(mb)     asm volatile("tcgen05.commit.cta_group::1.mbarrier::arrive::one.shared::cluster.b64 [%0];" :: "r"(mb) : "memory")
#define TC_WAIT_LD()      asm volatile("tcgen05.wait::ld.sync.aligned;" ::: "memory")
#define TC_WAIT_ST()      asm volatile("tcgen05.wait::st.sync.aligned;" ::: "memory")
#define TC_FENCE_BEFORE() asm volatile("tcgen05.fence::before_thread_sync;" ::: "memory")
#define TC_FENCE_AFTER()  asm volatile("tcgen05.fence::after_thread_sync;" ::: "memory")
#define FENCE_ASYNC()     asm volatile("fence.proxy.async.shared::cta;" ::: "memory")
#define NAMED_BAR(id, n)  asm volatile("bar.sync %0, %1;" :: "r"(id), "r"(n) : "memory")

__device__ __forceinline__ void mma_f16_ss(uint32_t d, uint64_t ad, uint64_t bd,
                                           uint32_t idesc, uint32_t en) {
    asm volatile(
        "{\n\t.reg .pred p;\n\t"
        "setp.ne.u32 p, %4, 0;\n\t"
        "tcgen05.mma.cta_group::1.kind::f16 [%0], %1, %2, %3, {%5,%5,%5,%5}, p;\n\t}"
        :: "r"(d), "l"(ad), "l"(bd), "r"(idesc), "r"(en), "r"(0u) : "memory");
}

#define TC_LD32(r, addr) \
    asm volatile( \
        "tcgen05.ld.sync.aligned.32x32b.x32.b32 " \
        "{%0,%1,%2,%3,%4,%5,%6,%7,%8,%9,%10,%11,%12,%13,%14,%15," \
        "%16,%17,%18,%19,%20,%21,%22,%23,%24,%25,%26,%27,%28,%29,%30,%31}, [%32];" \
        : "=r"((r)[0]),"=r"((r)[1]),"=r"((r)[2]),"=r"((r)[3]),"=r"((r)[4]),"=r"((r)[5]),"=r"((r)[6]),"=r"((r)[7]), \
          "=r"((r)[8]),"=r"((r)[9]),"=r"((r)[10]),"=r"((r)[11]),"=r"((r)[12]),"=r"((r)[13]),"=r"((r)[14]),"=r"((r)[15]), \
          "=r"((r)[16]),"=r"((r)[17]),"=r"((r)[18]),"=r"((r)[19]),"=r"((r)[20]),"=r"((r)[21]),"=r"((r)[22]),"=r"((r)[23]), \
          "=r"((r)[24]),"=r"((r)[25]),"=r"((r)[26]),"=r"((r)[27]),"=r"((r)[28]),"=r"((r)[29]),"=r"((r)[30]),"=r"((r)[31]) \
        : "r"(addr))

#define TC_ST32(addr, r) \
    asm volatile( \
        "tcgen05.st.sync.aligned.32x32b.x32.b32 [%0], " \
        "{%1,%2,%3,%4,%5,%6,%7,%8,%9,%10,%11,%12,%13,%14,%15,%16," \
        "%17,%18,%19,%20,%21,%22,%23,%24,%25,%26,%27,%28,%29,%30,%31,%32};" \
        :: "r"(addr), \
           "r"((r)[0]),"r"((r)[1]),"r"((r)[2]),"r"((r)[3]),"r"((r)[4]),"r"((r)[5]),"r"((r)[6]),"r"((r)[7]), \
           "r"((r)[8]),"r"((r)[9]),"r"((r)[10]),"r"((r)[11]),"r"((r)[12]),"r"((r)[13]),"r"((r)[14]),"r"((r)[15]), \
           "r"((r)[16]),"r"((r)[17]),"r"((r)[18]),"r"((r)[19]),"r"((r)[20]),"r"((r)[21]),"r"((r)[22]),"r"((r)[23]), \
           "r"((r)[24]),"r"((r)[25]),"r"((r)[26]),"r"((r)[27]),"r"((r)[28]),"r"((r)[29]),"r"((r)[30]),"r"((r)[31]) \
        : "memory")
#endif  // HAS_TC

__global__ void __launch_bounds__(384, 1) gemm_tc_kernel(const float* __restrict__ bias,
                                                         float* __restrict__ out) {
#if HAS_TC
    extern __shared__ char smem[];
    const uint32_t sbase = smem_u32(smem);
    const int tid = threadIdx.x;
    const int bn = blockIdx.x, bm = blockIdx.y;

    const uint32_t mb_full  = sbase + 16;   // [0..2], count 256
    const uint32_t mb_empty = sbase + 40;   // [0..2], count 1
    const uint32_t mb_chunk = sbase + 64;
    const uint32_t mb_final = sbase + 72;

    if (tid == 0) {
#pragma unroll
        for (int s = 0; s < STAGES; s++) {
            MBAR_INIT(mb_full + s * 8, 256);
            MBAR_INIT(mb_empty + s * 8, 1);
        }
        MBAR_INIT(mb_chunk, 1);
        MBAR_INIT(mb_final, 1);
    }
    if (tid >= 256 && tid < 288) { TC_ALLOC(sbase, 512); TC_RELINQ(); }
    __syncthreads();

    uint32_t tmem_base;
    asm volatile("ld.shared.b32 %0, [%1];" : "=r"(tmem_base) : "r"(sbase));

    float cs[NCHUNK];
    {
        float sw = quant_scale(4);
#pragma unroll
        for (int c = 0; c < NCHUNK; c++) cs[c] = quant_scale(c) * sw;
    }

    if (tid < 256) {
        // ================= PRODUCERS =================
        const __nv_bfloat16* gA = g_qx + (size_t)(bm * BT) * K_DIM;
        const __nv_bfloat16* gB = g_qw + (size_t)(bn * BT) * K_DIM;
        for (int t = 0; t < NITER; ++t) {
            const int slot = t % STAGES;
            if (t >= STAGES)
                mbar_wait(mb_empty + slot * 8, (uint32_t)(((t / STAGES) - 1) & 1));
            const uint32_t abase = sbase + SMEM_STAGE0 + slot * STAGE_BYTES;
            const uint32_t bbase = abase + A_STAGE_BYTES;
            const int kt = t * SK;
#pragma unroll
            for (int j = 0; j < 8; j++) {
                int ch = tid + j * 256;
                int row = ch >> 3, c16 = ch & 7;
                cp16(abase + swz(row * 128 + c16 * 16),
                     gA + (size_t)row * K_DIM + kt + c16 * 8);
            }
#pragma unroll
            for (int j = 0; j < 8; j++) {
                int ch = tid + j * 256;
                int row = ch >> 3, c16 = ch & 7;
                cp16(bbase + swz(row * 128 + c16 * 16),
                     gB + (size_t)row * K_DIM + kt + c16 * 8);
            }
            CPA_ARRIVE(mb_full + slot * 8);
        }
    } else {
        // ================= CONSUMER WARPGROUP (128 threads) =================
        const int ctid = tid - 256;
        const int cwarp = ctid >> 5;
        const uint32_t cwoff = (uint32_t)cwarp << 21;

        // 4 chunk segments of 16 stages each; rescale between segments
        for (int seg = 0; seg < 4; ++seg) {
            if (cwarp == 0) {
                const int i0 = seg * 16;
#pragma unroll 1
                for (int i = i0; i < i0 + 16; ++i) {
                    const int slot = i % STAGES;
                    mbar_wait(mb_full + slot * 8, (uint32_t)((i / STAGES) & 1));
                    if (elect1()) {
                        FENCE_ASYNC();
                        const uint32_t abase = sbase + SMEM_STAGE0 + slot * STAGE_BYTES;
                        const uint64_t ad = DESC_BASE_SW128 | ((uint64_t)(abase >> 4) & 0x3FFF);
                        const uint64_t bd = DESC_BASE_SW128 | ((uint64_t)((abase + A_STAGE_BYTES) >> 4) & 0x3FFF);
#pragma unroll
                        for (int h = 0; h < 2; h++) {
                            const uint32_t d = tmem_base + h * 256u;
                            const uint64_t adh = ad + h * 1024;
#pragma unroll
                            for (int k = 0; k < 4; k++) {
                                const uint32_t en = (i == 0 && k == 0) ? 0u : 1u;
                                mma_f16_ss(d, adh + k * 2, bd + k * 2, MMA_IDESC, en);
                            }
                        }
                        TC_COMMIT(mb_empty + slot * 8);
                    }
                    __syncwarp();
                }
                if (elect1()) {
                    if (seg < 3) TC_COMMIT(mb_chunk);
                    else         TC_COMMIT(mb_final);
                }
                __syncwarp();
            }

            if (seg < 3) {
                // rescale: all 4 consumer warps, converged per warp
                mbar_wait(mb_chunk, (uint32_t)(seg & 1));
                TC_FENCE_AFTER();
                const float ratio = cs[seg] / cs[seg + 1];
#pragma unroll
                for (int g = 0; g < 8; g++) {
                    uint32_t r[2][32];
                    TC_LD32(r[0], tmem_base + (g * 2) * 32);
                    TC_LD32(r[1], tmem_base + (g * 2 + 1) * 32);
                    TC_WAIT_LD();
#pragma unroll
                    for (int b = 0; b < 2; b++)
#pragma unroll
                        for (int j = 0; j < 32; j++)
                            r[b][j] = __float_as_uint(__uint_as_float(r[b][j]) * ratio);
                    TC_ST32(tmem_base + (g * 2) * 32 + cwoff, r[0]);
                    TC_ST32(tmem_base + (g * 2 + 1) * 32 + cwoff, r[1]);
                    TC_WAIT_ST();
                }
                TC_FENCE_BEFORE();
                NAMED_BAR(1, 128);
                TC_FENCE_AFTER();
            }
        }

        // epilogue
        mbar_wait(mb_final, 0u);
        TC_FENCE_AFTER();
        {
            const float fs = cs[3];
            const float* brow = bias + bn * BT;
#pragma unroll
            for (int h = 0; h < 2; h++) {
                const int row = bm * BT + h * 128 + ctid;
                float* orow = out + (size_t)row * N_DIM + bn * BT;
#pragma unroll
                for (int nb = 0; nb < 8; nb += 2) {
                    uint32_t a0[32], a1[32];
                    TC_LD32(a0, tmem_base + h * 256 + nb * 32);
                    TC_LD32(a1, tmem_base + h * 256 + (nb + 1) * 32);
                    TC_WAIT_LD();
#pragma unroll
                    for (int j = 0; j < 32; j += 4) {
                        float4 bb = *(const float4*)(brow + nb * 32 + j);
                        float4 v;
                        v.x = __uint_as_float(a0[j + 0]) * fs + bb.x;
                        v.y = __uint_as_float(a0[j + 1]) * fs + bb.y;
                        v.z = __uint_as_float(a0[j + 2]) * fs + bb.z;
                        v.w = __uint_as_float(a0[j + 3]) * fs + bb.w;
                        *(float4*)(orow + nb * 32 + j) = v;
                    }
#pragma unroll
                    for (int j = 0; j < 32; j += 4) {
                        float4 bb = *(const float4*)(brow + (nb + 1) * 32 + j);
                        float4 v;
                        v.x = __uint_as_float(a1[j + 0]) * fs + bb.x;
                        v.y = __uint_as_float(a1[j + 1]) * fs + bb.y;
                        v.z = __uint_as_float(a1[j + 2]) * fs + bb.z;
                        v.w = __uint_as_float(a1[j + 3]) * fs + bb.w;
                        *(float4*)(orow + (nb + 1) * 32 + j) = v;
                    }
                }
            }
            TC_FENCE_BEFORE();
        }
        NAMED_BAR(1, 128);
        if (cwarp == 0) {
            TC_DEALLOC(tmem_base, 512);
            if (elect1()) { MBAR_INVAL(mb_chunk); MBAR_INVAL(mb_final); }
        }
    }
#endif  // HAS_TC
}

// ---------------------------------------------------------------------------
extern "C" void kernel_launch(void* const* d_in, const int* in_sizes, int n_in,
                              void* d_out, int out_size) {
    const float* x = (const float*)d_in[0];
    const float* w = (const float*)d_in[1];
    const float* bias = (const float*)d_in[2];
    float* out = (float*)d_out;

    zero_kernel<<<1, 32>>>();
    absmax_kernel<<<ABS_X_BLOCKS + ABS_W_BLOCKS, 256>>>(x, w);
    quant_kernel<<<QNT_X_BLOCKS + QNT_W_BLOCKS, 256>>>(x, w);

    cudaFuncSetAttribute(gemm_tc_kernel,
                         cudaFuncAttributeMaxDynamicSharedMemorySize, SMEM_TOTAL);
    dim3 gtc(N_DIM / BT, M_DIM / BT);   // (16, 64)
    gemm_tc_kernel<<<gtc, 384, SMEM_TOTAL>>>(bias, out);
}